// round 1
// baseline (speedup 1.0000x reference)
#include <cuda_runtime.h>
#include <math.h>

#define NH 16
#define HD 128
#define TSEQ 2048
#define BB 2
#define DM 2048
#define NTOK (BB * TSEQ)          // 4096
#define QKV_COLS (3 * DM)         // 6144

// ---------------- scratch (device globals: no allocation allowed) ------------
__device__ float g_qkv[(size_t)NTOK * QKV_COLS];            // 100.7 MB
__device__ float g_q[(size_t)BB * NH * TSEQ * HD];          // 33.5 MB (pre-scaled by 1/sqrt(HD))
__device__ float g_k[(size_t)BB * NH * TSEQ * HD];
__device__ float g_v[(size_t)BB * NH * TSEQ * HD];
__device__ float g_ctx[(size_t)NTOK * DM];                  // 33.5 MB
__device__ float g_cos[TSEQ * (HD / 2)];
__device__ float g_sin[TSEQ * (HD / 2)];

// ---------------- RoPE table (double internally for accuracy) ----------------
__global__ void rope_table_kernel() {
    int idx = blockIdx.x * blockDim.x + threadIdx.x;
    if (idx >= TSEQ * (HD / 2)) return;
    int t = idx / (HD / 2);
    int i = idx % (HD / 2);
    double inv = exp(-log(10000.0) * (double)(2 * i) / (double)HD);
    double ang = (double)t * inv;
    g_cos[idx] = (float)cos(ang);
    g_sin[idx] = (float)sin(ang);
}

// ---------------- RoPE apply + head split -----------------------------------
// qkv: [NTOK][6144]  ->  g_q/g_k/g_v: [B*H][T][HD]; q additionally scaled.
__global__ void rope_split_kernel() {
    int token = blockIdx.x;          // 0..4095
    int h     = blockIdx.y;          // 0..15
    int d     = threadIdx.x;         // 0..127
    int b = token / TSEQ;
    int t = token - b * TSEQ;
    const float* base = g_qkv + (size_t)token * QKV_COLS;
    int dd = d & 63;
    float c = g_cos[t * 64 + dd];
    float s = g_sin[t * 64 + dd];
    float q1 = base[h * HD + dd];
    float q2 = base[h * HD + dd + 64];
    float k1 = base[DM + h * HD + dd];
    float k2 = base[DM + h * HD + dd + 64];
    float qo = (d < 64) ? (q1 * c - q2 * s) : (q1 * s + q2 * c);
    float ko = (d < 64) ? (k1 * c - k2 * s) : (k1 * s + k2 * c);
    size_t o = ((size_t)(b * NH + h) * TSEQ + t) * HD + d;
    g_q[o] = qo * 0.08838834764831845f;   // 1/sqrt(128)
    g_k[o] = ko;
    g_v[o] = base[2 * DM + h * HD + d];
}

// ---------------- SGEMM: C[M,N] = A[M,K] @ B[N,K]^T + bias[N] ---------------
// 128x128x8 tile, 256 threads, 8x8 microtile.
__global__ void __launch_bounds__(256)
sgemm_nt_bias(const float* __restrict__ A, const float* __restrict__ B,
              const float* __restrict__ bias, float* __restrict__ C,
              int M, int N, int K) {
    __shared__ float As[8][132];
    __shared__ float Bs[8][132];
    int bm = blockIdx.y * 128;
    int bn = blockIdx.x * 128;
    int tid = threadIdx.x;
    int tx = tid & 15, ty = tid >> 4;
    int lrow = tid >> 1;
    int lcol = (tid & 1) << 2;
    const float* Ap = A + (size_t)(bm + lrow) * K + lcol;
    const float* Bp = B + (size_t)(bn + lrow) * K + lcol;
    float acc[8][8];
#pragma unroll
    for (int i = 0; i < 8; i++)
#pragma unroll
        for (int j = 0; j < 8; j++) acc[i][j] = 0.f;

    for (int k0 = 0; k0 < K; k0 += 8) {
        float4 a4 = *(const float4*)(Ap + k0);
        float4 b4 = *(const float4*)(Bp + k0);
        As[lcol + 0][lrow] = a4.x; As[lcol + 1][lrow] = a4.y;
        As[lcol + 2][lrow] = a4.z; As[lcol + 3][lrow] = a4.w;
        Bs[lcol + 0][lrow] = b4.x; Bs[lcol + 1][lrow] = b4.y;
        Bs[lcol + 2][lrow] = b4.z; Bs[lcol + 3][lrow] = b4.w;
        __syncthreads();
#pragma unroll
        for (int k = 0; k < 8; k++) {
            float ra[8], rb[8];
            *(float4*)(ra)     = *(const float4*)&As[k][ty * 8];
            *(float4*)(ra + 4) = *(const float4*)&As[k][ty * 8 + 4];
            *(float4*)(rb)     = *(const float4*)&Bs[k][tx * 8];
            *(float4*)(rb + 4) = *(const float4*)&Bs[k][tx * 8 + 4];
#pragma unroll
            for (int i = 0; i < 8; i++)
#pragma unroll
                for (int j = 0; j < 8; j++) acc[i][j] += ra[i] * rb[j];
        }
        __syncthreads();
    }
#pragma unroll
    for (int i = 0; i < 8; i++) {
        float* Crow = C + (size_t)(bm + ty * 8 + i) * N + bn + tx * 8;
        float r[8];
#pragma unroll
        for (int j = 0; j < 8; j++) r[j] = acc[i][j] + bias[bn + tx * 8 + j];
        *(float4*)(Crow)     = *(const float4*)(r);
        *(float4*)(Crow + 4) = *(const float4*)(r + 4);
    }
}

// ---------------- Flash attention (causal), 64x64 tiles, fp32 ---------------
#define ATT_BM 64
#define ATT_BN 64
#define PS_STR (ATT_BM + 4)
#define ATT_SMEM_FLOATS (HD*ATT_BM + HD*ATT_BN + ATT_BN*HD + ATT_BN*PS_STR)
#define ATT_SMEM_BYTES (ATT_SMEM_FLOATS * 4)

__global__ void __launch_bounds__(256)
attn_kernel() {
    extern __shared__ float sm_att[];
    float* Qs = sm_att;                        // [HD][64]  (transposed)
    float* Ks = Qs + HD * ATT_BM;              // [HD][64]  (transposed)
    float* Vs = Ks + HD * ATT_BN;              // [64][HD]
    float* Ps = Vs + ATT_BN * HD;              // [64][68]  (P transposed: [j][m])

    int qb = blockIdx.x;           // q tile index
    int bh = blockIdx.y;           // b*16+h
    int tid = threadIdx.x;
    int tx = tid & 15, ty = tid >> 4;

    const float* Qg = g_q + ((size_t)bh * TSEQ + qb * ATT_BM) * HD;
#pragma unroll
    for (int it = 0; it < 8; it++) {
        int idx = tid + it * 256;
        int m = idx >> 5;
        int ds = (idx & 31) << 2;
        float4 v = *(const float4*)(Qg + m * HD + ds);
        Qs[(ds + 0) * ATT_BM + m] = v.x;
        Qs[(ds + 1) * ATT_BM + m] = v.y;
        Qs[(ds + 2) * ATT_BM + m] = v.z;
        Qs[(ds + 3) * ATT_BM + m] = v.w;
    }
    __syncthreads();

    float o[4][8];
#pragma unroll
    for (int i = 0; i < 4; i++)
#pragma unroll
        for (int c = 0; c < 8; c++) o[i][c] = 0.f;
    float mrow[4] = {-1e30f, -1e30f, -1e30f, -1e30f};
    float lrow[4] = {0.f, 0.f, 0.f, 0.f};

    for (int kb = 0; kb <= qb; kb++) {
        const float* Kg = g_k + ((size_t)bh * TSEQ + kb * ATT_BN) * HD;
        const float* Vg = g_v + ((size_t)bh * TSEQ + kb * ATT_BN) * HD;
#pragma unroll
        for (int it = 0; it < 8; it++) {
            int idx = tid + it * 256;
            int j = idx >> 5;
            int ds = (idx & 31) << 2;
            float4 kv = *(const float4*)(Kg + j * HD + ds);
            Ks[(ds + 0) * ATT_BN + j] = kv.x;
            Ks[(ds + 1) * ATT_BN + j] = kv.y;
            Ks[(ds + 2) * ATT_BN + j] = kv.z;
            Ks[(ds + 3) * ATT_BN + j] = kv.w;
            *(float4*)&Vs[j * HD + ds] = *(const float4*)(Vg + j * HD + ds);
        }
        __syncthreads();

        // ---- S = Q K^T (q pre-scaled) ----
        float s[4][4];
#pragma unroll
        for (int i = 0; i < 4; i++)
#pragma unroll
            for (int j = 0; j < 4; j++) s[i][j] = 0.f;
#pragma unroll 4
        for (int d = 0; d < HD; d++) {
            float4 qa = *(const float4*)&Qs[d * ATT_BM + ty * 4];
            float4 ka = *(const float4*)&Ks[d * ATT_BN + tx * 4];
            float ra[4] = {qa.x, qa.y, qa.z, qa.w};
            float rb[4] = {ka.x, ka.y, ka.z, ka.w};
#pragma unroll
            for (int i = 0; i < 4; i++)
#pragma unroll
                for (int j = 0; j < 4; j++) s[i][j] += ra[i] * rb[j];
        }

        // ---- causal mask (diagonal tile only) ----
        if (kb == qb) {
#pragma unroll
            for (int i = 0; i < 4; i++)
#pragma unroll
                for (int j = 0; j < 4; j++)
                    if (tx * 4 + j > ty * 4 + i) s[i][j] = -1e30f;
        }

        // ---- online softmax (row reduction across the 16 tx lanes) ----
#pragma unroll
        for (int i = 0; i < 4; i++) {
            float mx = fmaxf(fmaxf(s[i][0], s[i][1]), fmaxf(s[i][2], s[i][3]));
#pragma unroll
            for (int off = 1; off < 16; off <<= 1)
                mx = fmaxf(mx, __shfl_xor_sync(0xffffffffu, mx, off));
            float mnew = fmaxf(mrow[i], mx);
            float sum = 0.f;
#pragma unroll
            for (int j = 0; j < 4; j++) {
                s[i][j] = __expf(s[i][j] - mnew);
                sum += s[i][j];
            }
#pragma unroll
            for (int off = 1; off < 16; off <<= 1)
                sum += __shfl_xor_sync(0xffffffffu, sum, off);
            float alpha = __expf(mrow[i] - mnew);
            lrow[i] = lrow[i] * alpha + sum;
            mrow[i] = mnew;
#pragma unroll
            for (int c = 0; c < 8; c++) o[i][c] *= alpha;
        }

        // ---- write P transposed ----
#pragma unroll
        for (int i = 0; i < 4; i++)
#pragma unroll
            for (int j = 0; j < 4; j++)
                Ps[(tx * 4 + j) * PS_STR + ty * 4 + i] = s[i][j];
        __syncthreads();

        // ---- O += P @ V ----
#pragma unroll 2
        for (int j = 0; j < ATT_BN; j++) {
            float4 pa = *(const float4*)&Ps[j * PS_STR + ty * 4];
            float4 v0 = *(const float4*)&Vs[j * HD + tx * 8];
            float4 v1 = *(const float4*)&Vs[j * HD + tx * 8 + 4];
            float pr[4] = {pa.x, pa.y, pa.z, pa.w};
            float vv[8] = {v0.x, v0.y, v0.z, v0.w, v1.x, v1.y, v1.z, v1.w};
#pragma unroll
            for (int i = 0; i < 4; i++)
#pragma unroll
                for (int c = 0; c < 8; c++) o[i][c] += pr[i] * vv[c];
        }
        __syncthreads();
    }

    // ---- epilogue: normalize, write ctx[token][h*128+c] ----
    int b = bh >> 4, h = bh & 15;
#pragma unroll
    for (int i = 0; i < 4; i++) {
        float inv = 1.0f / lrow[i];
        int row = qb * ATT_BM + ty * 4 + i;
        float* Cp = g_ctx + ((size_t)(b * TSEQ + row)) * DM + h * HD + tx * 8;
        float r[8];
#pragma unroll
        for (int c = 0; c < 8; c++) r[c] = o[i][c] * inv;
        *(float4*)(Cp)     = *(const float4*)(r);
        *(float4*)(Cp + 4) = *(const float4*)(r + 4);
    }
}

// ---------------- launcher ---------------------------------------------------
extern "C" void kernel_launch(void* const* d_in, const int* in_sizes, int n_in,
                              void* d_out, int out_size) {
    const float* x    = (const float*)d_in[0];
    const float* Wqkv = (const float*)d_in[1];
    const float* bqkv = (const float*)d_in[2];
    const float* Wo   = (const float*)d_in[3];
    const float* bo   = (const float*)d_in[4];
    float* out = (float*)d_out;

    float *qkv_p, *ctx_p;
    cudaGetSymbolAddress((void**)&qkv_p, g_qkv);
    cudaGetSymbolAddress((void**)&ctx_p, g_ctx);

    // 1) RoPE table
    rope_table_kernel<<<(TSEQ * (HD / 2) + 255) / 256, 256>>>();

    // 2) QKV projection: [4096,6144] = x[4096,2048] @ Wqkv^T + bqkv
    {
        dim3 grid(QKV_COLS / 128, NTOK / 128);
        sgemm_nt_bias<<<grid, 256>>>(x, Wqkv, bqkv, qkv_p, NTOK, QKV_COLS, DM);
    }

    // 3) RoPE + head split
    {
        dim3 grid(NTOK, NH);
        rope_split_kernel<<<grid, HD>>>();
    }

    // 4) causal flash attention
    {
        cudaFuncSetAttribute(attn_kernel,
                             cudaFuncAttributeMaxDynamicSharedMemorySize,
                             ATT_SMEM_BYTES);
        dim3 grid(TSEQ / ATT_BM, BB * NH);
        attn_kernel<<<grid, 256, ATT_SMEM_BYTES>>>();
    }

    // 5) output projection: out[4096,2048] = ctx @ Wo^T + bo
    {
        dim3 grid(DM / 128, NTOK / 128);
        sgemm_nt_bias<<<grid, 256>>>(ctx_p, Wo, bo, out, NTOK, DM, DM);
    }
}

// round 3
// speedup vs baseline: 1.6783x; 1.6783x over previous
#include <cuda_runtime.h>
#include <cuda_bf16.h>
#include <math.h>
#include <stdint.h>

#define NH 16
#define HD 128
#define TSEQ 2048
#define BB 2
#define DM 2048
#define NTOK (BB * TSEQ)          // 4096
#define QKV_COLS (3 * DM)         // 6144

// ---------------- scratch (device globals: no allocation allowed) ------------
__device__ float g_qkv[(size_t)NTOK * QKV_COLS];
__device__ float g_q[(size_t)BB * NH * TSEQ * HD];
__device__ float g_k[(size_t)BB * NH * TSEQ * HD];
__device__ float g_v[(size_t)BB * NH * TSEQ * HD];
__device__ float g_ctx[(size_t)NTOK * DM];
__device__ float g_cos[TSEQ * (HD / 2)];
__device__ float g_sin[TSEQ * (HD / 2)];
__device__ __nv_bfloat16 g_xhi[(size_t)NTOK * DM];
__device__ __nv_bfloat16 g_xlo[(size_t)NTOK * DM];
__device__ __nv_bfloat16 g_wqkvhi[(size_t)QKV_COLS * DM];
__device__ __nv_bfloat16 g_wqkvlo[(size_t)QKV_COLS * DM];
__device__ __nv_bfloat16 g_wohi[(size_t)DM * DM];
__device__ __nv_bfloat16 g_wolo[(size_t)DM * DM];
__device__ __nv_bfloat16 g_chi[(size_t)NTOK * DM];
__device__ __nv_bfloat16 g_clo[(size_t)NTOK * DM];

// ---------------- helpers ------------------------------------------------------
__device__ __forceinline__ uint32_t smem_u32(const void* p) {
    uint32_t a;
    asm("{ .reg .u64 t; cvta.to.shared.u64 t, %1; cvt.u32.u64 %0, t; }"
        : "=r"(a) : "l"(p));
    return a;
}
__device__ __forceinline__ void cpa16(uint32_t dst, const void* src) {
    asm volatile("cp.async.cg.shared.global [%0], [%1], 16;" :: "r"(dst), "l"(src));
}
__device__ __forceinline__ void ldm_x4(uint32_t* r, uint32_t addr) {
    asm volatile("ldmatrix.sync.aligned.m8n8.x4.shared.b16 {%0,%1,%2,%3}, [%4];"
                 : "=r"(r[0]), "=r"(r[1]), "=r"(r[2]), "=r"(r[3]) : "r"(addr));
}
__device__ __forceinline__ void mma16816(float* d, const uint32_t* a, uint32_t b0, uint32_t b1) {
    asm volatile(
        "mma.sync.aligned.m16n8k16.row.col.f32.bf16.bf16.f32 "
        "{%0,%1,%2,%3}, {%4,%5,%6,%7}, {%8,%9}, {%0,%1,%2,%3};"
        : "+f"(d[0]), "+f"(d[1]), "+f"(d[2]), "+f"(d[3])
        : "r"(a[0]), "r"(a[1]), "r"(a[2]), "r"(a[3]), "r"(b0), "r"(b1));
}

// ---------------- RoPE table ----------------------------------------------------
__global__ void rope_table_kernel() {
    int idx = blockIdx.x * blockDim.x + threadIdx.x;
    if (idx >= TSEQ * (HD / 2)) return;
    int t = idx / (HD / 2);
    int i = idx % (HD / 2);
    double inv = exp(-log(10000.0) * (double)(2 * i) / (double)HD);
    double ang = (double)t * inv;
    g_cos[idx] = (float)cos(ang);
    g_sin[idx] = (float)sin(ang);
}

// ---------------- fp32 -> bf16 hi/lo split --------------------------------------
__global__ void convert_split(const float2* __restrict__ s,
                              __nv_bfloat162* __restrict__ hi,
                              __nv_bfloat162* __restrict__ lo, int n2) {
    int i = blockIdx.x * 256 + threadIdx.x;
    if (i >= n2) return;
    float2 v = s[i];
    __nv_bfloat16 h0 = __float2bfloat16_rn(v.x);
    __nv_bfloat16 h1 = __float2bfloat16_rn(v.y);
    __nv_bfloat16 l0 = __float2bfloat16_rn(v.x - __bfloat162float(h0));
    __nv_bfloat16 l1 = __float2bfloat16_rn(v.y - __bfloat162float(h1));
    hi[i] = __halves2bfloat162(h0, h1);
    lo[i] = __halves2bfloat162(l0, l1);
}

// ---------------- RoPE apply + head split ----------------------------------------
__global__ void rope_split_kernel() {
    int token = blockIdx.x;
    int h     = blockIdx.y;
    int d     = threadIdx.x;
    int b = token / TSEQ;
    int t = token - b * TSEQ;
    const float* base = g_qkv + (size_t)token * QKV_COLS;
    int dd = d & 63;
    float c = g_cos[t * 64 + dd];
    float s = g_sin[t * 64 + dd];
    float q1 = base[h * HD + dd];
    float q2 = base[h * HD + dd + 64];
    float k1 = base[DM + h * HD + dd];
    float k2 = base[DM + h * HD + dd + 64];
    float qo = (d < 64) ? (q1 * c - q2 * s) : (q1 * s + q2 * c);
    float ko = (d < 64) ? (k1 * c - k2 * s) : (k1 * s + k2 * c);
    size_t o = ((size_t)(b * NH + h) * TSEQ + t) * HD + d;
    g_q[o] = qo * 0.08838834764831845f;
    g_k[o] = ko;
    g_v[o] = base[2 * DM + h * HD + d];
}

// ---------------- HMMA bf16x3 GEMM: C[M,N] = A @ B^T + bias ---------------------
// A:[M,K] hi/lo, B:[N,K] hi/lo, K-major. 128x128x32 tile, 8 warps (4m x 2n),
// warp tile 32x64, mma.sync.m16n8k16.
#define GROW 40                           // padded smem row (bf16 elems)
#define GTILE_B (128 * GROW * 2)          // 10240 bytes
#define GSTAGE_B (4 * GTILE_B)            // 40960 bytes
#define G_SMEM_TOTAL (2 * GSTAGE_B)       // 81920 bytes

// load one 128x32 bf16 tile (64B/row) into padded smem rows
__device__ __forceinline__ void ld_tile(uint32_t dst, const __nv_bfloat16* g, int ldK) {
#pragma unroll
    for (int r = 0; r < 2; r++) {
        int idx = threadIdx.x + r * 256;   // 512 chunks of 16B
        int row = idx >> 2, c4 = idx & 3;
        cpa16(dst + (row * GROW + c4 * 8) * 2, g + (size_t)row * ldK + c4 * 8);
    }
}

__global__ void __launch_bounds__(256)
gemm_bf16x3(const __nv_bfloat16* __restrict__ Ahi, const __nv_bfloat16* __restrict__ Alo,
            const __nv_bfloat16* __restrict__ Bhi, const __nv_bfloat16* __restrict__ Blo,
            const float* __restrict__ bias, float* __restrict__ C,
            int M, int N, int K) {
    extern __shared__ __align__(128) char sm[];
    uint32_t sb = smem_u32(sm);
    int tid = threadIdx.x, wid = tid >> 5, lane = tid & 31;
    int wm = wid & 3, wn = wid >> 2;            // warp tile origin (wm*32, wn*64)
    int bm = blockIdx.y * 128, bn = blockIdx.x * 128;

    const __nv_bfloat16* Ah = Ahi + (size_t)bm * K;
    const __nv_bfloat16* Al = Alo + (size_t)bm * K;
    const __nv_bfloat16* Bh = Bhi + (size_t)bn * K;
    const __nv_bfloat16* Bl = Blo + (size_t)bn * K;

    float acc[2][8][4];
#pragma unroll
    for (int i = 0; i < 2; i++)
#pragma unroll
        for (int j = 0; j < 8; j++)
#pragma unroll
            for (int k = 0; k < 4; k++) acc[i][j][k] = 0.f;

    int nc = K / 32;
    // prologue: 2 stages
#pragma unroll
    for (int s = 0; s < 2; s++) {
        uint32_t st = sb + s * GSTAGE_B;
        ld_tile(st + 0 * GTILE_B, Ah + s * 32, K);
        ld_tile(st + 1 * GTILE_B, Al + s * 32, K);
        ld_tile(st + 2 * GTILE_B, Bh + s * 32, K);
        ld_tile(st + 3 * GTILE_B, Bl + s * 32, K);
        asm volatile("cp.async.commit_group;" ::: "memory");
    }

    // per-thread ldmatrix base offsets (lane -> row/col within 16x16 block)
    int lrow = lane & 15;                 // row within 16
    int lcol8 = (lane >> 4) * 8;          // 0 or 8

    for (int i = 0; i < nc; i++) {
        if (i == nc - 1) asm volatile("cp.async.wait_group 0;" ::: "memory");
        else             asm volatile("cp.async.wait_group 1;" ::: "memory");
        __syncthreads();

        uint32_t st = sb + (uint32_t)(i & 1) * GSTAGE_B;
        uint32_t sAh = st, sAl = st + GTILE_B, sBh = st + 2 * GTILE_B, sBl = st + 3 * GTILE_B;

#pragma unroll
        for (int ks = 0; ks < 2; ks++) {
            int kc = ks * 16 + lcol8;
            uint32_t ah[2][4], al[2][4], bh[4][4], bl[4][4];
#pragma unroll
            for (int mi = 0; mi < 2; mi++) {
                int r = wm * 32 + mi * 16 + lrow;
                ldm_x4(ah[mi], sAh + (r * GROW + kc) * 2);
                ldm_x4(al[mi], sAl + (r * GROW + kc) * 2);
            }
#pragma unroll
            for (int nb = 0; nb < 4; nb++) {
                int r = wn * 64 + nb * 16 + lrow;
                ldm_x4(bh[nb], sBh + (r * GROW + kc) * 2);
                ldm_x4(bl[nb], sBl + (r * GROW + kc) * 2);
            }
#pragma unroll
            for (int mi = 0; mi < 2; mi++)
#pragma unroll
                for (int nb = 0; nb < 4; nb++) {
                    mma16816(acc[mi][2 * nb + 0], ah[mi], bh[nb][0], bh[nb][2]);
                    mma16816(acc[mi][2 * nb + 1], ah[mi], bh[nb][1], bh[nb][3]);
                    mma16816(acc[mi][2 * nb + 0], ah[mi], bl[nb][0], bl[nb][2]);
                    mma16816(acc[mi][2 * nb + 1], ah[mi], bl[nb][1], bl[nb][3]);
                    mma16816(acc[mi][2 * nb + 0], al[mi], bh[nb][0], bh[nb][2]);
                    mma16816(acc[mi][2 * nb + 1], al[mi], bh[nb][1], bh[nb][3]);
                }
        }
        __syncthreads();
        if (i + 2 < nc) {
            ld_tile(st + 0 * GTILE_B, Ah + (i + 2) * 32, K);
            ld_tile(st + 1 * GTILE_B, Al + (i + 2) * 32, K);
            ld_tile(st + 2 * GTILE_B, Bh + (i + 2) * 32, K);
            ld_tile(st + 3 * GTILE_B, Bl + (i + 2) * 32, K);
            asm volatile("cp.async.commit_group;" ::: "memory");
        }
    }

    // epilogue: registers -> C with bias
    int qrow = lane >> 2, qcol = (lane & 3) * 2;
#pragma unroll
    for (int mi = 0; mi < 2; mi++) {
#pragma unroll
        for (int ni = 0; ni < 8; ni++) {
            int c = bn + wn * 64 + ni * 8 + qcol;
            float b0 = bias[c], b1 = bias[c + 1];
            int r0 = bm + wm * 32 + mi * 16 + qrow;
            float2 v0 = make_float2(acc[mi][ni][0] + b0, acc[mi][ni][1] + b1);
            float2 v1 = make_float2(acc[mi][ni][2] + b0, acc[mi][ni][3] + b1);
            *(float2*)(C + (size_t)r0 * N + c) = v0;
            *(float2*)(C + (size_t)(r0 + 8) * N + c) = v1;
        }
    }
}

// ---------------- Flash attention (causal), 64x64 tiles, fp32 -------------------
#define ATT_BM 64
#define ATT_BN 64
#define PS_STR (ATT_BM + 4)
#define ATT_SMEM_FLOATS (HD*ATT_BM + HD*ATT_BN + ATT_BN*HD + ATT_BN*PS_STR)
#define ATT_SMEM_BYTES (ATT_SMEM_FLOATS * 4)

__global__ void __launch_bounds__(256)
attn_kernel() {
    extern __shared__ float sm_att[];
    float* Qs = sm_att;
    float* Ks = Qs + HD * ATT_BM;
    float* Vs = Ks + HD * ATT_BN;
    float* Ps = Vs + ATT_BN * HD;

    int qb = blockIdx.x;
    int bh = blockIdx.y;
    int tid = threadIdx.x;
    int tx = tid & 15, ty = tid >> 4;

    const float* Qg = g_q + ((size_t)bh * TSEQ + qb * ATT_BM) * HD;
#pragma unroll
    for (int it = 0; it < 8; it++) {
        int idx = tid + it * 256;
        int m = idx >> 5;
        int ds = (idx & 31) << 2;
        float4 v = *(const float4*)(Qg + m * HD + ds);
        Qs[(ds + 0) * ATT_BM + m] = v.x;
        Qs[(ds + 1) * ATT_BM + m] = v.y;
        Qs[(ds + 2) * ATT_BM + m] = v.z;
        Qs[(ds + 3) * ATT_BM + m] = v.w;
    }
    __syncthreads();

    float o[4][8];
#pragma unroll
    for (int i = 0; i < 4; i++)
#pragma unroll
        for (int c = 0; c < 8; c++) o[i][c] = 0.f;
    float mrow[4] = {-1e30f, -1e30f, -1e30f, -1e30f};
    float lrow[4] = {0.f, 0.f, 0.f, 0.f};

    for (int kb = 0; kb <= qb; kb++) {
        const float* Kg = g_k + ((size_t)bh * TSEQ + kb * ATT_BN) * HD;
        const float* Vg = g_v + ((size_t)bh * TSEQ + kb * ATT_BN) * HD;
#pragma unroll
        for (int it = 0; it < 8; it++) {
            int idx = tid + it * 256;
            int j = idx >> 5;
            int ds = (idx & 31) << 2;
            float4 kv = *(const float4*)(Kg + j * HD + ds);
            Ks[(ds + 0) * ATT_BN + j] = kv.x;
            Ks[(ds + 1) * ATT_BN + j] = kv.y;
            Ks[(ds + 2) * ATT_BN + j] = kv.z;
            Ks[(ds + 3) * ATT_BN + j] = kv.w;
            *(float4*)&Vs[j * HD + ds] = *(const float4*)(Vg + j * HD + ds);
        }
        __syncthreads();

        float s[4][4];
#pragma unroll
        for (int i = 0; i < 4; i++)
#pragma unroll
            for (int j = 0; j < 4; j++) s[i][j] = 0.f;
#pragma unroll 4
        for (int d = 0; d < HD; d++) {
            float4 qa = *(const float4*)&Qs[d * ATT_BM + ty * 4];
            float4 ka = *(const float4*)&Ks[d * ATT_BN + tx * 4];
            float ra[4] = {qa.x, qa.y, qa.z, qa.w};
            float rb[4] = {ka.x, ka.y, ka.z, ka.w};
#pragma unroll
            for (int i = 0; i < 4; i++)
#pragma unroll
                for (int j = 0; j < 4; j++) s[i][j] += ra[i] * rb[j];
        }

        if (kb == qb) {
#pragma unroll
            for (int i = 0; i < 4; i++)
#pragma unroll
                for (int j = 0; j < 4; j++)
                    if (tx * 4 + j > ty * 4 + i) s[i][j] = -1e30f;
        }

#pragma unroll
        for (int i = 0; i < 4; i++) {
            float mx = fmaxf(fmaxf(s[i][0], s[i][1]), fmaxf(s[i][2], s[i][3]));
#pragma unroll
            for (int off = 1; off < 16; off <<= 1)
                mx = fmaxf(mx, __shfl_xor_sync(0xffffffffu, mx, off));
            float mnew = fmaxf(mrow[i], mx);
            float sum = 0.f;
#pragma unroll
            for (int j = 0; j < 4; j++) {
                s[i][j] = __expf(s[i][j] - mnew);
                sum += s[i][j];
            }
#pragma unroll
            for (int off = 1; off < 16; off <<= 1)
                sum += __shfl_xor_sync(0xffffffffu, sum, off);
            float alpha = __expf(mrow[i] - mnew);
            lrow[i] = lrow[i] * alpha + sum;
            mrow[i] = mnew;
#pragma unroll
            for (int c = 0; c < 8; c++) o[i][c] *= alpha;
        }

#pragma unroll
        for (int i = 0; i < 4; i++)
#pragma unroll
            for (int j = 0; j < 4; j++)
                Ps[(tx * 4 + j) * PS_STR + ty * 4 + i] = s[i][j];
        __syncthreads();

#pragma unroll 2
        for (int j = 0; j < ATT_BN; j++) {
            float4 pa = *(const float4*)&Ps[j * PS_STR + ty * 4];
            float4 v0 = *(const float4*)&Vs[j * HD + tx * 8];
            float4 v1 = *(const float4*)&Vs[j * HD + tx * 8 + 4];
            float pr[4] = {pa.x, pa.y, pa.z, pa.w};
            float vv[8] = {v0.x, v0.y, v0.z, v0.w, v1.x, v1.y, v1.z, v1.w};
#pragma unroll
            for (int i = 0; i < 4; i++)
#pragma unroll
                for (int c = 0; c < 8; c++) o[i][c] += pr[i] * vv[c];
        }
        __syncthreads();
    }

    int b = bh >> 4, h = bh & 15;
#pragma unroll
    for (int i = 0; i < 4; i++) {
        float inv = 1.0f / lrow[i];
        int row = qb * ATT_BM + ty * 4 + i;
        float* Cp = g_ctx + ((size_t)(b * TSEQ + row)) * DM + h * HD + tx * 8;
        float r[8];
#pragma unroll
        for (int c = 0; c < 8; c++) r[c] = o[i][c] * inv;
        *(float4*)(Cp)     = *(const float4*)(r);
        *(float4*)(Cp + 4) = *(const float4*)(r + 4);
    }
}

// ---------------- launcher --------------------------------------------------------
extern "C" void kernel_launch(void* const* d_in, const int* in_sizes, int n_in,
                              void* d_out, int out_size) {
    const float* x    = (const float*)d_in[0];
    const float* Wqkv = (const float*)d_in[1];
    const float* bqkv = (const float*)d_in[2];
    const float* Wo   = (const float*)d_in[3];
    const float* bo   = (const float*)d_in[4];
    float* out = (float*)d_out;

    float *qkv_p, *ctx_p;
    cudaGetSymbolAddress((void**)&qkv_p, g_qkv);
    cudaGetSymbolAddress((void**)&ctx_p, g_ctx);
    __nv_bfloat16 *xhi, *xlo, *whi, *wlo, *wohi, *wolo, *chi, *clo;
    cudaGetSymbolAddress((void**)&xhi, g_xhi);
    cudaGetSymbolAddress((void**)&xlo, g_xlo);
    cudaGetSymbolAddress((void**)&whi, g_wqkvhi);
    cudaGetSymbolAddress((void**)&wlo, g_wqkvlo);
    cudaGetSymbolAddress((void**)&wohi, g_wohi);
    cudaGetSymbolAddress((void**)&wolo, g_wolo);
    cudaGetSymbolAddress((void**)&chi, g_chi);
    cudaGetSymbolAddress((void**)&clo, g_clo);

    cudaFuncSetAttribute(gemm_bf16x3,
                         cudaFuncAttributeMaxDynamicSharedMemorySize, G_SMEM_TOTAL);
    cudaFuncSetAttribute(attn_kernel,
                         cudaFuncAttributeMaxDynamicSharedMemorySize, ATT_SMEM_BYTES);

    // 1) RoPE table
    rope_table_kernel<<<(TSEQ * (HD / 2) + 255) / 256, 256>>>();

    // 2) split x and Wqkv into bf16 hi/lo
    {
        int n2 = (NTOK * DM) / 2;
        convert_split<<<(n2 + 255) / 256, 256>>>((const float2*)x,
            (__nv_bfloat162*)xhi, (__nv_bfloat162*)xlo, n2);
        n2 = (QKV_COLS * DM) / 2;
        convert_split<<<(n2 + 255) / 256, 256>>>((const float2*)Wqkv,
            (__nv_bfloat162*)whi, (__nv_bfloat162*)wlo, n2);
    }

    // 3) QKV projection on tensor cores (HMMA)
    {
        dim3 grid(QKV_COLS / 128, NTOK / 128);
        gemm_bf16x3<<<grid, 256, G_SMEM_TOTAL>>>(xhi, xlo, whi, wlo, bqkv, qkv_p,
                                                 NTOK, QKV_COLS, DM);
    }

    // 4) RoPE + head split
    {
        dim3 grid(NTOK, NH);
        rope_split_kernel<<<grid, HD>>>();
    }

    // 5) causal flash attention
    {
        dim3 grid(TSEQ / ATT_BM, BB * NH);
        attn_kernel<<<grid, 256, ATT_SMEM_BYTES>>>();
    }

    // 6) split ctx and Wo
    {
        int n2 = (NTOK * DM) / 2;
        convert_split<<<(n2 + 255) / 256, 256>>>((const float2*)ctx_p,
            (__nv_bfloat162*)chi, (__nv_bfloat162*)clo, n2);
        n2 = (DM * DM) / 2;
        convert_split<<<(n2 + 255) / 256, 256>>>((const float2*)Wo,
            (__nv_bfloat162*)wohi, (__nv_bfloat162*)wolo, n2);
    }

    // 7) output projection on tensor cores (HMMA)
    {
        dim3 grid(DM / 128, NTOK / 128);
        gemm_bf16x3<<<grid, 256, G_SMEM_TOTAL>>>(chi, clo, wohi, wolo, bo, out,
                                                 NTOK, DM, DM);
    }
}

// round 4
// speedup vs baseline: 2.7188x; 1.6200x over previous
#include <cuda_runtime.h>
#include <cuda_bf16.h>
#include <math.h>
#include <stdint.h>

#define NH 16
#define HD 128
#define TSEQ 2048
#define BB 2
#define DM 2048
#define NTOK (BB * TSEQ)          // 4096
#define QKV_COLS (3 * DM)         // 6144

// ---------------- scratch (device globals: no allocation allowed) ------------
__device__ float g_qkv[(size_t)NTOK * QKV_COLS];
__device__ float g_ctx[(size_t)NTOK * DM];
__device__ float g_cos[TSEQ * (HD / 2)];
__device__ float g_sin[TSEQ * (HD / 2)];
// bf16 hi/lo split operands for projections
__device__ __nv_bfloat16 g_xhi[(size_t)NTOK * DM];
__device__ __nv_bfloat16 g_xlo[(size_t)NTOK * DM];
__device__ __nv_bfloat16 g_wqkvhi[(size_t)QKV_COLS * DM];
__device__ __nv_bfloat16 g_wqkvlo[(size_t)QKV_COLS * DM];
__device__ __nv_bfloat16 g_wohi[(size_t)DM * DM];
__device__ __nv_bfloat16 g_wolo[(size_t)DM * DM];
__device__ __nv_bfloat16 g_chi[(size_t)NTOK * DM];
__device__ __nv_bfloat16 g_clo[(size_t)NTOK * DM];
// attention operands (bf16 hi/lo). q/k: [BH][T][HD]; vt: [BH][HD][T]
#define BH_T_HD ((size_t)BB * NH * TSEQ * HD)
__device__ __nv_bfloat16 g_qhi[BH_T_HD];
__device__ __nv_bfloat16 g_qlo[BH_T_HD];
__device__ __nv_bfloat16 g_khi[BH_T_HD];
__device__ __nv_bfloat16 g_klo[BH_T_HD];
__device__ __nv_bfloat16 g_vthi[BH_T_HD];
__device__ __nv_bfloat16 g_vtlo[BH_T_HD];

// ---------------- helpers ------------------------------------------------------
__device__ __forceinline__ uint32_t smem_u32(const void* p) {
    uint32_t a;
    asm("{ .reg .u64 t; cvta.to.shared.u64 t, %1; cvt.u32.u64 %0, t; }"
        : "=r"(a) : "l"(p));
    return a;
}
__device__ __forceinline__ void cpa16(uint32_t dst, const void* src) {
    asm volatile("cp.async.cg.shared.global [%0], [%1], 16;" :: "r"(dst), "l"(src));
}
__device__ __forceinline__ void ldm_x4(uint32_t* r, uint32_t addr) {
    asm volatile("ldmatrix.sync.aligned.m8n8.x4.shared.b16 {%0,%1,%2,%3}, [%4];"
                 : "=r"(r[0]), "=r"(r[1]), "=r"(r[2]), "=r"(r[3]) : "r"(addr));
}
__device__ __forceinline__ void mma16816(float* d, const uint32_t* a, uint32_t b0, uint32_t b1) {
    asm volatile(
        "mma.sync.aligned.m16n8k16.row.col.f32.bf16.bf16.f32 "
        "{%0,%1,%2,%3}, {%4,%5,%6,%7}, {%8,%9}, {%0,%1,%2,%3};"
        : "+f"(d[0]), "+f"(d[1]), "+f"(d[2]), "+f"(d[3])
        : "r"(a[0]), "r"(a[1]), "r"(a[2]), "r"(a[3]), "r"(b0), "r"(b1));
}
// pack two fp32 -> bf16x2 (lo in low half)
__device__ __forceinline__ uint32_t packbf(float lo, float hi) {
    uint32_t r;
    asm("cvt.rn.bf16x2.f32 %0, %1, %2;" : "=r"(r) : "f"(hi), "f"(lo));
    return r;
}
// hi/lo split of a fp32 pair into two bf16x2 regs
__device__ __forceinline__ void split2(float p0, float p1, uint32_t& ph, uint32_t& pl) {
    __nv_bfloat16 h0 = __float2bfloat16_rn(p0);
    __nv_bfloat16 h1 = __float2bfloat16_rn(p1);
    ph = ((uint32_t)__bfloat16_as_ushort(h1) << 16) | __bfloat16_as_ushort(h0);
    pl = packbf(p0 - __bfloat162float(h0), p1 - __bfloat162float(h1));
}

// ---------------- RoPE table ----------------------------------------------------
__global__ void rope_table_kernel() {
    int idx = blockIdx.x * blockDim.x + threadIdx.x;
    if (idx >= TSEQ * (HD / 2)) return;
    int t = idx / (HD / 2);
    int i = idx % (HD / 2);
    double inv = exp(-log(10000.0) * (double)(2 * i) / (double)HD);
    double ang = (double)t * inv;
    g_cos[idx] = (float)cos(ang);
    g_sin[idx] = (float)sin(ang);
}

// ---------------- fp32 -> bf16 hi/lo split --------------------------------------
__global__ void convert_split(const float2* __restrict__ s,
                              __nv_bfloat162* __restrict__ hi,
                              __nv_bfloat162* __restrict__ lo, int n2) {
    int i = blockIdx.x * 256 + threadIdx.x;
    if (i >= n2) return;
    float2 v = s[i];
    __nv_bfloat16 h0 = __float2bfloat16_rn(v.x);
    __nv_bfloat16 h1 = __float2bfloat16_rn(v.y);
    __nv_bfloat16 l0 = __float2bfloat16_rn(v.x - __bfloat162float(h0));
    __nv_bfloat16 l1 = __float2bfloat16_rn(v.y - __bfloat162float(h1));
    hi[i] = __halves2bfloat162(h0, h1);
    lo[i] = __halves2bfloat162(l0, l1);
}

// ---------------- RoPE apply + head split + bf16 hi/lo + V transpose ------------
__global__ void rope_split_kernel() {
    int token = blockIdx.x;
    int h     = blockIdx.y;
    int d     = threadIdx.x;
    int b = token / TSEQ;
    int t = token - b * TSEQ;
    const float* base = g_qkv + (size_t)token * QKV_COLS;
    int dd = d & 63;
    float c = g_cos[t * 64 + dd];
    float s = g_sin[t * 64 + dd];
    float q1 = base[h * HD + dd];
    float q2 = base[h * HD + dd + 64];
    float k1 = base[DM + h * HD + dd];
    float k2 = base[DM + h * HD + dd + 64];
    float qo = ((d < 64) ? (q1 * c - q2 * s) : (q1 * s + q2 * c)) * 0.08838834764831845f;
    float ko = (d < 64) ? (k1 * c - k2 * s) : (k1 * s + k2 * c);
    float vo = base[2 * DM + h * HD + d];
    int bh = b * NH + h;
    size_t o = ((size_t)bh * TSEQ + t) * HD + d;
    __nv_bfloat16 qh = __float2bfloat16_rn(qo);
    __nv_bfloat16 kh = __float2bfloat16_rn(ko);
    __nv_bfloat16 vh = __float2bfloat16_rn(vo);
    g_qhi[o] = qh; g_qlo[o] = __float2bfloat16_rn(qo - __bfloat162float(qh));
    g_khi[o] = kh; g_klo[o] = __float2bfloat16_rn(ko - __bfloat162float(kh));
    size_t ov = ((size_t)bh * HD + d) * TSEQ + t;
    g_vthi[ov] = vh; g_vtlo[ov] = __float2bfloat16_rn(vo - __bfloat162float(vh));
}

// ---------------- HMMA bf16x3 GEMM: C[M,N] = A @ B^T + bias ---------------------
#define GROW 40
#define GTILE_B (128 * GROW * 2)
#define GSTAGE_B (4 * GTILE_B)
#define G_SMEM_TOTAL (2 * GSTAGE_B)

__device__ __forceinline__ void ld_tile(uint32_t dst, const __nv_bfloat16* g, int ldK) {
#pragma unroll
    for (int r = 0; r < 2; r++) {
        int idx = threadIdx.x + r * 256;
        int row = idx >> 2, c4 = idx & 3;
        cpa16(dst + (row * GROW + c4 * 8) * 2, g + (size_t)row * ldK + c4 * 8);
    }
}

__global__ void __launch_bounds__(256)
gemm_bf16x3(const __nv_bfloat16* __restrict__ Ahi, const __nv_bfloat16* __restrict__ Alo,
            const __nv_bfloat16* __restrict__ Bhi, const __nv_bfloat16* __restrict__ Blo,
            const float* __restrict__ bias, float* __restrict__ C,
            int M, int N, int K) {
    extern __shared__ __align__(128) char sm[];
    uint32_t sb = smem_u32(sm);
    int tid = threadIdx.x, wid = tid >> 5, lane = tid & 31;
    int wm = wid & 3, wn = wid >> 2;
    int bm = blockIdx.y * 128, bn = blockIdx.x * 128;

    const __nv_bfloat16* Ah = Ahi + (size_t)bm * K;
    const __nv_bfloat16* Al = Alo + (size_t)bm * K;
    const __nv_bfloat16* Bh = Bhi + (size_t)bn * K;
    const __nv_bfloat16* Bl = Blo + (size_t)bn * K;

    float acc[2][8][4];
#pragma unroll
    for (int i = 0; i < 2; i++)
#pragma unroll
        for (int j = 0; j < 8; j++)
#pragma unroll
            for (int k = 0; k < 4; k++) acc[i][j][k] = 0.f;

    int nc = K / 32;
#pragma unroll
    for (int s = 0; s < 2; s++) {
        uint32_t st = sb + s * GSTAGE_B;
        ld_tile(st + 0 * GTILE_B, Ah + s * 32, K);
        ld_tile(st + 1 * GTILE_B, Al + s * 32, K);
        ld_tile(st + 2 * GTILE_B, Bh + s * 32, K);
        ld_tile(st + 3 * GTILE_B, Bl + s * 32, K);
        asm volatile("cp.async.commit_group;" ::: "memory");
    }

    int lrow = lane & 15;
    int lcol8 = (lane >> 4) * 8;

    for (int i = 0; i < nc; i++) {
        if (i == nc - 1) asm volatile("cp.async.wait_group 0;" ::: "memory");
        else             asm volatile("cp.async.wait_group 1;" ::: "memory");
        __syncthreads();

        uint32_t st = sb + (uint32_t)(i & 1) * GSTAGE_B;
        uint32_t sAh = st, sAl = st + GTILE_B, sBh = st + 2 * GTILE_B, sBl = st + 3 * GTILE_B;

#pragma unroll
        for (int ks = 0; ks < 2; ks++) {
            int kc = ks * 16 + lcol8;
            uint32_t ah[2][4], al[2][4], bh[4][4], bl[4][4];
#pragma unroll
            for (int mi = 0; mi < 2; mi++) {
                int r = wm * 32 + mi * 16 + lrow;
                ldm_x4(ah[mi], sAh + (r * GROW + kc) * 2);
                ldm_x4(al[mi], sAl + (r * GROW + kc) * 2);
            }
#pragma unroll
            for (int nb = 0; nb < 4; nb++) {
                int r = wn * 64 + nb * 16 + lrow;
                ldm_x4(bh[nb], sBh + (r * GROW + kc) * 2);
                ldm_x4(bl[nb], sBl + (r * GROW + kc) * 2);
            }
#pragma unroll
            for (int mi = 0; mi < 2; mi++)
#pragma unroll
                for (int nb = 0; nb < 4; nb++) {
                    mma16816(acc[mi][2 * nb + 0], ah[mi], bh[nb][0], bh[nb][2]);
                    mma16816(acc[mi][2 * nb + 1], ah[mi], bh[nb][1], bh[nb][3]);
                    mma16816(acc[mi][2 * nb + 0], ah[mi], bl[nb][0], bl[nb][2]);
                    mma16816(acc[mi][2 * nb + 1], ah[mi], bl[nb][1], bl[nb][3]);
                    mma16816(acc[mi][2 * nb + 0], al[mi], bh[nb][0], bh[nb][2]);
                    mma16816(acc[mi][2 * nb + 1], al[mi], bh[nb][1], bh[nb][3]);
                }
        }
        __syncthreads();
        if (i + 2 < nc) {
            ld_tile(st + 0 * GTILE_B, Ah + (i + 2) * 32, K);
            ld_tile(st + 1 * GTILE_B, Al + (i + 2) * 32, K);
            ld_tile(st + 2 * GTILE_B, Bh + (i + 2) * 32, K);
            ld_tile(st + 3 * GTILE_B, Bl + (i + 2) * 32, K);
            asm volatile("cp.async.commit_group;" ::: "memory");
        }
    }

    int qrow = lane >> 2, qcol = (lane & 3) * 2;
#pragma unroll
    for (int mi = 0; mi < 2; mi++) {
#pragma unroll
        for (int ni = 0; ni < 8; ni++) {
            int c = bn + wn * 64 + ni * 8 + qcol;
            float b0 = bias[c], b1 = bias[c + 1];
            int r0 = bm + wm * 32 + mi * 16 + qrow;
            float2 v0 = make_float2(acc[mi][ni][0] + b0, acc[mi][ni][1] + b1);
            float2 v1 = make_float2(acc[mi][ni][2] + b0, acc[mi][ni][3] + b1);
            *(float2*)(C + (size_t)r0 * N + c) = v0;
            *(float2*)(C + (size_t)(r0 + 8) * N + c) = v1;
        }
    }
}

// ---------------- HMMA flash attention (causal) ---------------------------------
// CTA: 128 q-rows x 64-key tiles; 8 warps, each one m16 slice, full N=64.
#define ABM 128
#define ABN 64
#define QSTR 136
#define KSTR 136
#define VSTR 72
#define SM_QH 0
#define SM_QL (SM_QH + ABM * QSTR * 2)          // 34816
#define SM_KH (SM_QL + ABM * QSTR * 2)          // 69632
#define SM_KL (SM_KH + ABN * KSTR * 2)          // 87040
#define SM_VH (SM_KL + ABN * KSTR * 2)          // 104448
#define SM_VL (SM_VH + HD * VSTR * 2)           // 122880
#define ATT_SMEM (SM_VL + HD * VSTR * 2)        // 141312

__global__ void __launch_bounds__(256)
attn_mma_kernel() {
    extern __shared__ __align__(128) char smA[];
    uint32_t sb = smem_u32(smA);
    int tid = threadIdx.x, wid = tid >> 5, lane = tid & 31;
    int qb = blockIdx.x;           // q tile (128 rows)
    int bh = blockIdx.y;
    int lrow = lane & 15;
    int lcol8 = (lane >> 4) * 8;
    int qrow = lane >> 2, qcol = (lane & 3) * 2;

    // ---- load Q tile (hi, lo) ----
    {
        const __nv_bfloat16* Qh = g_qhi + ((size_t)bh * TSEQ + qb * ABM) * HD;
        const __nv_bfloat16* Ql = g_qlo + ((size_t)bh * TSEQ + qb * ABM) * HD;
#pragma unroll
        for (int i = 0; i < 8; i++) {
            int idx = tid + i * 256;
            int row = idx >> 4, c = idx & 15;
            cpa16(sb + SM_QH + (row * QSTR + c * 8) * 2, Qh + (size_t)row * HD + c * 8);
            cpa16(sb + SM_QL + (row * QSTR + c * 8) * 2, Ql + (size_t)row * HD + c * 8);
        }
        asm volatile("cp.async.commit_group;" ::: "memory");
        asm volatile("cp.async.wait_group 0;" ::: "memory");
        __syncthreads();
    }

    float o[16][4];
#pragma unroll
    for (int i = 0; i < 16; i++)
#pragma unroll
        for (int j = 0; j < 4; j++) o[i][j] = 0.f;
    float m0 = -1e30f, m1 = -1e30f, l0 = 0.f, l1 = 0.f;

    int nkb = 2 * qb + 2;
    for (int kb = 0; kb < nkb; kb++) {
        // ---- load K tile [64][128] and Vt tile [128][64] ----
        {
            const __nv_bfloat16* Kh = g_khi + ((size_t)bh * TSEQ + kb * ABN) * HD;
            const __nv_bfloat16* Kl = g_klo + ((size_t)bh * TSEQ + kb * ABN) * HD;
#pragma unroll
            for (int i = 0; i < 4; i++) {
                int idx = tid + i * 256;
                int row = idx >> 4, c = idx & 15;
                cpa16(sb + SM_KH + (row * KSTR + c * 8) * 2, Kh + (size_t)row * HD + c * 8);
                cpa16(sb + SM_KL + (row * KSTR + c * 8) * 2, Kl + (size_t)row * HD + c * 8);
            }
            const __nv_bfloat16* Vh = g_vthi + (size_t)bh * HD * TSEQ + kb * ABN;
            const __nv_bfloat16* Vl = g_vtlo + (size_t)bh * HD * TSEQ + kb * ABN;
#pragma unroll
            for (int i = 0; i < 4; i++) {
                int idx = tid + i * 256;
                int row = idx >> 3, c = idx & 7;
                cpa16(sb + SM_VH + (row * VSTR + c * 8) * 2, Vh + (size_t)row * TSEQ + c * 8);
                cpa16(sb + SM_VL + (row * VSTR + c * 8) * 2, Vl + (size_t)row * TSEQ + c * 8);
            }
            asm volatile("cp.async.commit_group;" ::: "memory");
            asm volatile("cp.async.wait_group 0;" ::: "memory");
            __syncthreads();
        }

        // ---- S = Q K^T (bf16x3, fp32 acc) ----
        float s[8][4];
#pragma unroll
        for (int i = 0; i < 8; i++)
#pragma unroll
            for (int j = 0; j < 4; j++) s[i][j] = 0.f;
#pragma unroll
        for (int kc = 0; kc < 8; kc++) {
            uint32_t ah[4], al[4];
            uint32_t qa = sb + SM_QH + ((wid * 16 + lrow) * QSTR + kc * 16 + lcol8) * 2;
            uint32_t qa2 = sb + SM_QL + ((wid * 16 + lrow) * QSTR + kc * 16 + lcol8) * 2;
            ldm_x4(ah, qa);
            ldm_x4(al, qa2);
#pragma unroll
            for (int nb = 0; nb < 4; nb++) {
                uint32_t bhh[4], bll[4];
                uint32_t ka = sb + SM_KH + ((nb * 16 + lrow) * KSTR + kc * 16 + lcol8) * 2;
                uint32_t ka2 = sb + SM_KL + ((nb * 16 + lrow) * KSTR + kc * 16 + lcol8) * 2;
                ldm_x4(bhh, ka);
                ldm_x4(bll, ka2);
                mma16816(s[2 * nb + 0], ah, bhh[0], bhh[2]);
                mma16816(s[2 * nb + 1], ah, bhh[1], bhh[3]);
                mma16816(s[2 * nb + 0], ah, bll[0], bll[2]);
                mma16816(s[2 * nb + 1], ah, bll[1], bll[3]);
                mma16816(s[2 * nb + 0], al, bhh[0], bhh[2]);
                mma16816(s[2 * nb + 1], al, bhh[1], bhh[3]);
            }
        }

        // ---- causal mask (only tiles overlapping the diagonal) ----
        if (kb >= 2 * qb) {
            int rg = qb * ABM + wid * 16 + qrow;
#pragma unroll
            for (int nb = 0; nb < 8; nb++) {
#pragma unroll
                for (int e = 0; e < 2; e++) {
                    int col = kb * ABN + nb * 8 + qcol + e;
                    if (col > rg)     s[nb][e]     = -1e30f;
                    if (col > rg + 8) s[nb][2 + e] = -1e30f;
                }
            }
        }

        // ---- online softmax (rows qrow and qrow+8) ----
        float mx0 = -1e30f, mx1 = -1e30f;
#pragma unroll
        for (int nb = 0; nb < 8; nb++) {
            mx0 = fmaxf(mx0, fmaxf(s[nb][0], s[nb][1]));
            mx1 = fmaxf(mx1, fmaxf(s[nb][2], s[nb][3]));
        }
        mx0 = fmaxf(mx0, __shfl_xor_sync(0xffffffffu, mx0, 1));
        mx0 = fmaxf(mx0, __shfl_xor_sync(0xffffffffu, mx0, 2));
        mx1 = fmaxf(mx1, __shfl_xor_sync(0xffffffffu, mx1, 1));
        mx1 = fmaxf(mx1, __shfl_xor_sync(0xffffffffu, mx1, 2));
        float mn0 = fmaxf(m0, mx0), mn1 = fmaxf(m1, mx1);
        float a0 = __expf(m0 - mn0), a1 = __expf(m1 - mn1);
        float sum0 = 0.f, sum1 = 0.f;
#pragma unroll
        for (int nb = 0; nb < 8; nb++) {
            s[nb][0] = __expf(s[nb][0] - mn0); sum0 += s[nb][0];
            s[nb][1] = __expf(s[nb][1] - mn0); sum0 += s[nb][1];
            s[nb][2] = __expf(s[nb][2] - mn1); sum1 += s[nb][2];
            s[nb][3] = __expf(s[nb][3] - mn1); sum1 += s[nb][3];
        }
        sum0 += __shfl_xor_sync(0xffffffffu, sum0, 1);
        sum0 += __shfl_xor_sync(0xffffffffu, sum0, 2);
        sum1 += __shfl_xor_sync(0xffffffffu, sum1, 1);
        sum1 += __shfl_xor_sync(0xffffffffu, sum1, 2);
        l0 = l0 * a0 + sum0; l1 = l1 * a1 + sum1;
        m0 = mn0; m1 = mn1;
#pragma unroll
        for (int nb = 0; nb < 16; nb++) {
            o[nb][0] *= a0; o[nb][1] *= a0;
            o[nb][2] *= a1; o[nb][3] *= a1;
        }

        // ---- O += P @ V (P acc frags -> A operand frags, hi/lo split) ----
#pragma unroll
        for (int kk = 0; kk < 4; kk++) {
            uint32_t pah[4], pal[4];
            split2(s[2 * kk][0],     s[2 * kk][1],     pah[0], pal[0]);
            split2(s[2 * kk][2],     s[2 * kk][3],     pah[1], pal[1]);
            split2(s[2 * kk + 1][0], s[2 * kk + 1][1], pah[2], pal[2]);
            split2(s[2 * kk + 1][2], s[2 * kk + 1][3], pah[3], pal[3]);
#pragma unroll
            for (int blk = 0; blk < 8; blk++) {
                uint32_t vb[4], vl[4];
                uint32_t va = sb + SM_VH + ((blk * 16 + lrow) * VSTR + kk * 16 + lcol8) * 2;
                uint32_t va2 = sb + SM_VL + ((blk * 16 + lrow) * VSTR + kk * 16 + lcol8) * 2;
                ldm_x4(vb, va);
                ldm_x4(vl, va2);
                mma16816(o[2 * blk + 0], pah, vb[0], vb[2]);
                mma16816(o[2 * blk + 1], pah, vb[1], vb[3]);
                mma16816(o[2 * blk + 0], pah, vl[0], vl[2]);
                mma16816(o[2 * blk + 1], pah, vl[1], vl[3]);
                mma16816(o[2 * blk + 0], pal, vb[0], vb[2]);
                mma16816(o[2 * blk + 1], pal, vb[1], vb[3]);
            }
        }
        __syncthreads();   // before next kb overwrites K/V smem
    }

    // ---- epilogue: normalize and write ctx ----
    float inv0 = 1.0f / l0, inv1 = 1.0f / l1;
    int b = bh >> 4, h = bh & 15;
    int r0 = qb * ABM + wid * 16 + qrow;
    float* base0 = g_ctx + ((size_t)(b * TSEQ + r0)) * DM + h * HD + qcol;
    float* base1 = g_ctx + ((size_t)(b * TSEQ + r0 + 8)) * DM + h * HD + qcol;
#pragma unroll
    for (int nb = 0; nb < 16; nb++) {
        *(float2*)(base0 + nb * 8) = make_float2(o[nb][0] * inv0, o[nb][1] * inv0);
        *(float2*)(base1 + nb * 8) = make_float2(o[nb][2] * inv1, o[nb][3] * inv1);
    }
}

// ---------------- launcher --------------------------------------------------------
extern "C" void kernel_launch(void* const* d_in, const int* in_sizes, int n_in,
                              void* d_out, int out_size) {
    const float* x    = (const float*)d_in[0];
    const float* Wqkv = (const float*)d_in[1];
    const float* bqkv = (const float*)d_in[2];
    const float* Wo   = (const float*)d_in[3];
    const float* bo   = (const float*)d_in[4];
    float* out = (float*)d_out;

    float *qkv_p, *ctx_p;
    cudaGetSymbolAddress((void**)&qkv_p, g_qkv);
    cudaGetSymbolAddress((void**)&ctx_p, g_ctx);
    __nv_bfloat16 *xhi, *xlo, *whi, *wlo, *wohi, *wolo, *chi, *clo;
    cudaGetSymbolAddress((void**)&xhi, g_xhi);
    cudaGetSymbolAddress((void**)&xlo, g_xlo);
    cudaGetSymbolAddress((void**)&whi, g_wqkvhi);
    cudaGetSymbolAddress((void**)&wlo, g_wqkvlo);
    cudaGetSymbolAddress((void**)&wohi, g_wohi);
    cudaGetSymbolAddress((void**)&wolo, g_wolo);
    cudaGetSymbolAddress((void**)&chi, g_chi);
    cudaGetSymbolAddress((void**)&clo, g_clo);

    cudaFuncSetAttribute(gemm_bf16x3,
                         cudaFuncAttributeMaxDynamicSharedMemorySize, G_SMEM_TOTAL);
    cudaFuncSetAttribute(attn_mma_kernel,
                         cudaFuncAttributeMaxDynamicSharedMemorySize, ATT_SMEM);

    // 1) RoPE table
    rope_table_kernel<<<(TSEQ * (HD / 2) + 255) / 256, 256>>>();

    // 2) split x and Wqkv into bf16 hi/lo
    {
        int n2 = (NTOK * DM) / 2;
        convert_split<<<(n2 + 255) / 256, 256>>>((const float2*)x,
            (__nv_bfloat162*)xhi, (__nv_bfloat162*)xlo, n2);
        n2 = (QKV_COLS * DM) / 2;
        convert_split<<<(n2 + 255) / 256, 256>>>((const float2*)Wqkv,
            (__nv_bfloat162*)whi, (__nv_bfloat162*)wlo, n2);
    }

    // 3) QKV projection (HMMA)
    {
        dim3 grid(QKV_COLS / 128, NTOK / 128);
        gemm_bf16x3<<<grid, 256, G_SMEM_TOTAL>>>(xhi, xlo, whi, wlo, bqkv, qkv_p,
                                                 NTOK, QKV_COLS, DM);
    }

    // 4) RoPE + head split + bf16 split + V transpose
    {
        dim3 grid(NTOK, NH);
        rope_split_kernel<<<grid, HD>>>();
    }

    // 5) causal flash attention (HMMA)
    {
        dim3 grid(TSEQ / ABM, BB * NH);
        attn_mma_kernel<<<grid, 256, ATT_SMEM>>>();
    }

    // 6) split ctx and Wo
    {
        int n2 = (NTOK * DM) / 2;
        convert_split<<<(n2 + 255) / 256, 256>>>((const float2*)ctx_p,
            (__nv_bfloat162*)chi, (__nv_bfloat162*)clo, n2);
        n2 = (DM * DM) / 2;
        convert_split<<<(n2 + 255) / 256, 256>>>((const float2*)Wo,
            (__nv_bfloat162*)wohi, (__nv_bfloat162*)wolo, n2);
    }

    // 7) output projection (HMMA)
    {
        dim3 grid(DM / 128, NTOK / 128);
        gemm_bf16x3<<<grid, 256, G_SMEM_TOTAL>>>(chi, clo, wohi, wolo, bo, out,
                                                 NTOK, DM, DM);
    }
}

// round 5
// speedup vs baseline: 3.5825x; 1.3177x over previous
#include <cuda_runtime.h>
#include <cuda_bf16.h>
#include <cuda_fp16.h>
#include <math.h>
#include <stdint.h>

#define NH 16
#define HD 128
#define TSEQ 2048
#define BB 2
#define DM 2048
#define NTOK (BB * TSEQ)          // 4096
#define QKV_COLS (3 * DM)         // 6144

// ---------------- scratch (device globals: no allocation allowed) ------------
__device__ float g_qkv[(size_t)NTOK * QKV_COLS];
__device__ float g_ctx[(size_t)NTOK * DM];
__device__ float g_cos[TSEQ * (HD / 2)];
__device__ float g_sin[TSEQ * (HD / 2)];
// fp16 operands for projections (A: hi only; B: hi+lo)
__device__ __half g_xh[(size_t)NTOK * DM];
__device__ __half g_wqkvh[(size_t)QKV_COLS * DM];
__device__ __half g_wqkvl[(size_t)QKV_COLS * DM];
__device__ __half g_woh[(size_t)DM * DM];
__device__ __half g_wol[(size_t)DM * DM];
__device__ __half g_ch[(size_t)NTOK * DM];
// attention operands (bf16 hi/lo). q/k: [BH][T][HD]; vt: [BH][HD][T]
#define BH_T_HD ((size_t)BB * NH * TSEQ * HD)
__device__ __nv_bfloat16 g_qhi[BH_T_HD];
__device__ __nv_bfloat16 g_qlo[BH_T_HD];
__device__ __nv_bfloat16 g_khi[BH_T_HD];
__device__ __nv_bfloat16 g_klo[BH_T_HD];
__device__ __nv_bfloat16 g_vthi[BH_T_HD];
__device__ __nv_bfloat16 g_vtlo[BH_T_HD];

// ---------------- helpers ------------------------------------------------------
__device__ __forceinline__ uint32_t smem_u32(const void* p) {
    uint32_t a;
    asm("{ .reg .u64 t; cvta.to.shared.u64 t, %1; cvt.u32.u64 %0, t; }"
        : "=r"(a) : "l"(p));
    return a;
}
__device__ __forceinline__ void cpa16(uint32_t dst, const void* src) {
    asm volatile("cp.async.cg.shared.global [%0], [%1], 16;" :: "r"(dst), "l"(src));
}
__device__ __forceinline__ void ldm_x4(uint32_t* r, uint32_t addr) {
    asm volatile("ldmatrix.sync.aligned.m8n8.x4.shared.b16 {%0,%1,%2,%3}, [%4];"
                 : "=r"(r[0]), "=r"(r[1]), "=r"(r[2]), "=r"(r[3]) : "r"(addr));
}
__device__ __forceinline__ void mma16816(float* d, const uint32_t* a, uint32_t b0, uint32_t b1) {
    asm volatile(
        "mma.sync.aligned.m16n8k16.row.col.f32.bf16.bf16.f32 "
        "{%0,%1,%2,%3}, {%4,%5,%6,%7}, {%8,%9}, {%0,%1,%2,%3};"
        : "+f"(d[0]), "+f"(d[1]), "+f"(d[2]), "+f"(d[3])
        : "r"(a[0]), "r"(a[1]), "r"(a[2]), "r"(a[3]), "r"(b0), "r"(b1));
}
__device__ __forceinline__ void mma16816h(float* d, const uint32_t* a, uint32_t b0, uint32_t b1) {
    asm volatile(
        "mma.sync.aligned.m16n8k16.row.col.f32.f16.f16.f32 "
        "{%0,%1,%2,%3}, {%4,%5,%6,%7}, {%8,%9}, {%0,%1,%2,%3};"
        : "+f"(d[0]), "+f"(d[1]), "+f"(d[2]), "+f"(d[3])
        : "r"(a[0]), "r"(a[1]), "r"(a[2]), "r"(a[3]), "r"(b0), "r"(b1));
}
__device__ __forceinline__ uint32_t packbf(float lo, float hi) {
    uint32_t r;
    asm("cvt.rn.bf16x2.f32 %0, %1, %2;" : "=r"(r) : "f"(hi), "f"(lo));
    return r;
}
__device__ __forceinline__ void split2(float p0, float p1, uint32_t& ph, uint32_t& pl) {
    __nv_bfloat16 h0 = __float2bfloat16_rn(p0);
    __nv_bfloat16 h1 = __float2bfloat16_rn(p1);
    ph = ((uint32_t)__bfloat16_as_ushort(h1) << 16) | __bfloat16_as_ushort(h0);
    pl = packbf(p0 - __bfloat162float(h0), p1 - __bfloat162float(h1));
}

// ---------------- RoPE table ----------------------------------------------------
__global__ void rope_table_kernel() {
    int idx = blockIdx.x * blockDim.x + threadIdx.x;
    if (idx >= TSEQ * (HD / 2)) return;
    int t = idx / (HD / 2);
    int i = idx % (HD / 2);
    double inv = exp(-log(10000.0) * (double)(2 * i) / (double)HD);
    double ang = (double)t * inv;
    g_cos[idx] = (float)cos(ang);
    g_sin[idx] = (float)sin(ang);
}

// ---------------- fp32 -> fp16 converts ------------------------------------------
__global__ void convert_hi_fp16(const float2* __restrict__ s, __half2* __restrict__ hi, int n2) {
    int i = blockIdx.x * 256 + threadIdx.x;
    if (i >= n2) return;
    float2 v = s[i];
    hi[i] = __floats2half2_rn(v.x, v.y);
}
__global__ void convert_split_fp16(const float2* __restrict__ s,
                                   __half2* __restrict__ hi,
                                   __half2* __restrict__ lo, int n2) {
    int i = blockIdx.x * 256 + threadIdx.x;
    if (i >= n2) return;
    float2 v = s[i];
    __half h0 = __float2half_rn(v.x);
    __half h1 = __float2half_rn(v.y);
    hi[i] = __halves2half2(h0, h1);
    lo[i] = __floats2half2_rn(v.x - __half2float(h0), v.y - __half2float(h1));
}

// ---------------- RoPE apply + head split + bf16 hi/lo + V transpose ------------
__global__ void rope_split_kernel() {
    int token = blockIdx.x;
    int h     = blockIdx.y;
    int d     = threadIdx.x;
    int b = token / TSEQ;
    int t = token - b * TSEQ;
    const float* base = g_qkv + (size_t)token * QKV_COLS;
    int dd = d & 63;
    float c = g_cos[t * 64 + dd];
    float s = g_sin[t * 64 + dd];
    float q1 = base[h * HD + dd];
    float q2 = base[h * HD + dd + 64];
    float k1 = base[DM + h * HD + dd];
    float k2 = base[DM + h * HD + dd + 64];
    float qo = ((d < 64) ? (q1 * c - q2 * s) : (q1 * s + q2 * c)) * 0.08838834764831845f;
    float ko = (d < 64) ? (k1 * c - k2 * s) : (k1 * s + k2 * c);
    float vo = base[2 * DM + h * HD + d];
    int bh = b * NH + h;
    size_t o = ((size_t)bh * TSEQ + t) * HD + d;
    __nv_bfloat16 qh = __float2bfloat16_rn(qo);
    __nv_bfloat16 kh = __float2bfloat16_rn(ko);
    __nv_bfloat16 vh = __float2bfloat16_rn(vo);
    g_qhi[o] = qh; g_qlo[o] = __float2bfloat16_rn(qo - __bfloat162float(qh));
    g_khi[o] = kh; g_klo[o] = __float2bfloat16_rn(ko - __bfloat162float(kh));
    size_t ov = ((size_t)bh * HD + d) * TSEQ + t;
    g_vthi[ov] = vh; g_vtlo[ov] = __float2bfloat16_rn(vo - __bfloat162float(vh));
}

// ---------------- HMMA fp16 2-term GEMM: C = Ah @ (Bh + Bl)^T + bias ------------
// A:[M,K] fp16 hi, B:[N,K] fp16 hi/lo, K-major. 128x128x64 tile, 8 warps (4m x 2n),
// warp tile 32x64, mma.sync.m16n8k16.f16.
#define GROW 72                           // padded smem row (fp16 elems), 144B stride
#define GTILE_B (128 * GROW * 2)          // 18432 bytes
#define GSTAGE_B (3 * GTILE_B)            // 55296 bytes (Ah, Bh, Bl)
#define G_SMEM_TOTAL (2 * GSTAGE_B)       // 110592 bytes

// load one 128x64 fp16 tile (128B/row) into padded smem rows
__device__ __forceinline__ void ld_tile64(uint32_t dst, const __half* g, int ldK) {
#pragma unroll
    for (int r = 0; r < 4; r++) {
        int idx = threadIdx.x + r * 256;   // 1024 chunks of 16B
        int row = idx >> 3, c = idx & 7;
        cpa16(dst + (row * GROW + c * 8) * 2, g + (size_t)row * ldK + c * 8);
    }
}

__global__ void __launch_bounds__(256, 2)
gemm_fp16_2t(const __half* __restrict__ Ah,
             const __half* __restrict__ Bhi, const __half* __restrict__ Blo,
             const float* __restrict__ bias, float* __restrict__ C,
             int M, int N, int K) {
    extern __shared__ __align__(128) char sm[];
    uint32_t sb = smem_u32(sm);
    int tid = threadIdx.x, wid = tid >> 5, lane = tid & 31;
    int wm = wid & 3, wn = wid >> 2;            // warp tile origin (wm*32, wn*64)
    int bm = blockIdx.y * 128, bn = blockIdx.x * 128;

    const __half* Ap = Ah  + (size_t)bm * K;
    const __half* Bh = Bhi + (size_t)bn * K;
    const __half* Bl = Blo + (size_t)bn * K;

    float acc[2][8][4];
#pragma unroll
    for (int i = 0; i < 2; i++)
#pragma unroll
        for (int j = 0; j < 8; j++)
#pragma unroll
            for (int k = 0; k < 4; k++) acc[i][j][k] = 0.f;

    int nc = K / 64;
#pragma unroll
    for (int s = 0; s < 2; s++) {
        uint32_t st = sb + s * GSTAGE_B;
        ld_tile64(st + 0 * GTILE_B, Ap + s * 64, K);
        ld_tile64(st + 1 * GTILE_B, Bh + s * 64, K);
        ld_tile64(st + 2 * GTILE_B, Bl + s * 64, K);
        asm volatile("cp.async.commit_group;" ::: "memory");
    }

    int lrow = lane & 15;
    int lcol8 = (lane >> 4) * 8;

    for (int i = 0; i < nc; i++) {
        if (i == nc - 1) asm volatile("cp.async.wait_group 0;" ::: "memory");
        else             asm volatile("cp.async.wait_group 1;" ::: "memory");
        __syncthreads();

        uint32_t st = sb + (uint32_t)(i & 1) * GSTAGE_B;
        uint32_t sA = st, sBh = st + GTILE_B, sBl = st + 2 * GTILE_B;

#pragma unroll
        for (int ks = 0; ks < 4; ks++) {
            int kc = ks * 16 + lcol8;
            uint32_t a[2][4], bh[4][4], bl[4][4];
#pragma unroll
            for (int mi = 0; mi < 2; mi++) {
                int r = wm * 32 + mi * 16 + lrow;
                ldm_x4(a[mi], sA + (r * GROW + kc) * 2);
            }
#pragma unroll
            for (int nb = 0; nb < 4; nb++) {
                int r = wn * 64 + nb * 16 + lrow;
                ldm_x4(bh[nb], sBh + (r * GROW + kc) * 2);
                ldm_x4(bl[nb], sBl + (r * GROW + kc) * 2);
            }
#pragma unroll
            for (int mi = 0; mi < 2; mi++)
#pragma unroll
                for (int nb = 0; nb < 4; nb++) {
                    mma16816h(acc[mi][2 * nb + 0], a[mi], bh[nb][0], bh[nb][2]);
                    mma16816h(acc[mi][2 * nb + 1], a[mi], bh[nb][1], bh[nb][3]);
                    mma16816h(acc[mi][2 * nb + 0], a[mi], bl[nb][0], bl[nb][2]);
                    mma16816h(acc[mi][2 * nb + 1], a[mi], bl[nb][1], bl[nb][3]);
                }
        }
        __syncthreads();
        if (i + 2 < nc) {
            int k0 = (i + 2) * 64;
            ld_tile64(st + 0 * GTILE_B, Ap + k0, K);
            ld_tile64(st + 1 * GTILE_B, Bh + k0, K);
            ld_tile64(st + 2 * GTILE_B, Bl + k0, K);
            asm volatile("cp.async.commit_group;" ::: "memory");
        }
    }

    int qrow = lane >> 2, qcol = (lane & 3) * 2;
#pragma unroll
    for (int mi = 0; mi < 2; mi++) {
#pragma unroll
        for (int ni = 0; ni < 8; ni++) {
            int c = bn + wn * 64 + ni * 8 + qcol;
            float b0 = bias[c], b1 = bias[c + 1];
            int r0 = bm + wm * 32 + mi * 16 + qrow;
            float2 v0 = make_float2(acc[mi][ni][0] + b0, acc[mi][ni][1] + b1);
            float2 v1 = make_float2(acc[mi][ni][2] + b0, acc[mi][ni][3] + b1);
            *(float2*)(C + (size_t)r0 * N + c) = v0;
            *(float2*)(C + (size_t)(r0 + 8) * N + c) = v1;
        }
    }
}

// ---------------- HMMA flash attention (causal), bf16x3 -------------------------
#define ABM 128
#define ABN 64
#define QSTR 136
#define KSTR 136
#define VSTR 72
#define SM_QH 0
#define SM_QL (SM_QH + ABM * QSTR * 2)          // 34816
#define SM_KH (SM_QL + ABM * QSTR * 2)          // 69632
#define SM_KL (SM_KH + ABN * KSTR * 2)          // 87040
#define SM_VH (SM_KL + ABN * KSTR * 2)          // 104448
#define SM_VL (SM_VH + HD * VSTR * 2)           // 122880
#define ATT_SMEM (SM_VL + HD * VSTR * 2)        // 141312

__global__ void __launch_bounds__(256)
attn_mma_kernel() {
    extern __shared__ __align__(128) char smA[];
    uint32_t sb = smem_u32(smA);
    int tid = threadIdx.x, wid = tid >> 5, lane = tid & 31;
    int qb = blockIdx.x;
    int bh = blockIdx.y;
    int lrow = lane & 15;
    int lcol8 = (lane >> 4) * 8;
    int qrow = lane >> 2, qcol = (lane & 3) * 2;

    {
        const __nv_bfloat16* Qh = g_qhi + ((size_t)bh * TSEQ + qb * ABM) * HD;
        const __nv_bfloat16* Ql = g_qlo + ((size_t)bh * TSEQ + qb * ABM) * HD;
#pragma unroll
        for (int i = 0; i < 8; i++) {
            int idx = tid + i * 256;
            int row = idx >> 4, c = idx & 15;
            cpa16(sb + SM_QH + (row * QSTR + c * 8) * 2, Qh + (size_t)row * HD + c * 8);
            cpa16(sb + SM_QL + (row * QSTR + c * 8) * 2, Ql + (size_t)row * HD + c * 8);
        }
        asm volatile("cp.async.commit_group;" ::: "memory");
        asm volatile("cp.async.wait_group 0;" ::: "memory");
        __syncthreads();
    }

    float o[16][4];
#pragma unroll
    for (int i = 0; i < 16; i++)
#pragma unroll
        for (int j = 0; j < 4; j++) o[i][j] = 0.f;
    float m0 = -1e30f, m1 = -1e30f, l0 = 0.f, l1 = 0.f;

    int nkb = 2 * qb + 2;
    for (int kb = 0; kb < nkb; kb++) {
        {
            const __nv_bfloat16* Kh = g_khi + ((size_t)bh * TSEQ + kb * ABN) * HD;
            const __nv_bfloat16* Kl = g_klo + ((size_t)bh * TSEQ + kb * ABN) * HD;
#pragma unroll
            for (int i = 0; i < 4; i++) {
                int idx = tid + i * 256;
                int row = idx >> 4, c = idx & 15;
                cpa16(sb + SM_KH + (row * KSTR + c * 8) * 2, Kh + (size_t)row * HD + c * 8);
                cpa16(sb + SM_KL + (row * KSTR + c * 8) * 2, Kl + (size_t)row * HD + c * 8);
            }
            const __nv_bfloat16* Vh = g_vthi + (size_t)bh * HD * TSEQ + kb * ABN;
            const __nv_bfloat16* Vl = g_vtlo + (size_t)bh * HD * TSEQ + kb * ABN;
#pragma unroll
            for (int i = 0; i < 4; i++) {
                int idx = tid + i * 256;
                int row = idx >> 3, c = idx & 7;
                cpa16(sb + SM_VH + (row * VSTR + c * 8) * 2, Vh + (size_t)row * TSEQ + c * 8);
                cpa16(sb + SM_VL + (row * VSTR + c * 8) * 2, Vl + (size_t)row * TSEQ + c * 8);
            }
            asm volatile("cp.async.commit_group;" ::: "memory");
            asm volatile("cp.async.wait_group 0;" ::: "memory");
            __syncthreads();
        }

        float s[8][4];
#pragma unroll
        for (int i = 0; i < 8; i++)
#pragma unroll
            for (int j = 0; j < 4; j++) s[i][j] = 0.f;
#pragma unroll
        for (int kc = 0; kc < 8; kc++) {
            uint32_t ah[4], al[4];
            uint32_t qa = sb + SM_QH + ((wid * 16 + lrow) * QSTR + kc * 16 + lcol8) * 2;
            uint32_t qa2 = sb + SM_QL + ((wid * 16 + lrow) * QSTR + kc * 16 + lcol8) * 2;
            ldm_x4(ah, qa);
            ldm_x4(al, qa2);
#pragma unroll
            for (int nb = 0; nb < 4; nb++) {
                uint32_t bhh[4], bll[4];
                uint32_t ka = sb + SM_KH + ((nb * 16 + lrow) * KSTR + kc * 16 + lcol8) * 2;
                uint32_t ka2 = sb + SM_KL + ((nb * 16 + lrow) * KSTR + kc * 16 + lcol8) * 2;
                ldm_x4(bhh, ka);
                ldm_x4(bll, ka2);
                mma16816(s[2 * nb + 0], ah, bhh[0], bhh[2]);
                mma16816(s[2 * nb + 1], ah, bhh[1], bhh[3]);
                mma16816(s[2 * nb + 0], ah, bll[0], bll[2]);
                mma16816(s[2 * nb + 1], ah, bll[1], bll[3]);
                mma16816(s[2 * nb + 0], al, bhh[0], bhh[2]);
                mma16816(s[2 * nb + 1], al, bhh[1], bhh[3]);
            }
        }

        if (kb >= 2 * qb) {
            int rg = qb * ABM + wid * 16 + qrow;
#pragma unroll
            for (int nb = 0; nb < 8; nb++) {
#pragma unroll
                for (int e = 0; e < 2; e++) {
                    int col = kb * ABN + nb * 8 + qcol + e;
                    if (col > rg)     s[nb][e]     = -1e30f;
                    if (col > rg + 8) s[nb][2 + e] = -1e30f;
                }
            }
        }

        float mx0 = -1e30f, mx1 = -1e30f;
#pragma unroll
        for (int nb = 0; nb < 8; nb++) {
            mx0 = fmaxf(mx0, fmaxf(s[nb][0], s[nb][1]));
            mx1 = fmaxf(mx1, fmaxf(s[nb][2], s[nb][3]));
        }
        mx0 = fmaxf(mx0, __shfl_xor_sync(0xffffffffu, mx0, 1));
        mx0 = fmaxf(mx0, __shfl_xor_sync(0xffffffffu, mx0, 2));
        mx1 = fmaxf(mx1, __shfl_xor_sync(0xffffffffu, mx1, 1));
        mx1 = fmaxf(mx1, __shfl_xor_sync(0xffffffffu, mx1, 2));
        float mn0 = fmaxf(m0, mx0), mn1 = fmaxf(m1, mx1);
        float a0 = __expf(m0 - mn0), a1 = __expf(m1 - mn1);
        float sum0 = 0.f, sum1 = 0.f;
#pragma unroll
        for (int nb = 0; nb < 8; nb++) {
            s[nb][0] = __expf(s[nb][0] - mn0); sum0 += s[nb][0];
            s[nb][1] = __expf(s[nb][1] - mn0); sum0 += s[nb][1];
            s[nb][2] = __expf(s[nb][2] - mn1); sum1 += s[nb][2];
            s[nb][3] = __expf(s[nb][3] - mn1); sum1 += s[nb][3];
        }
        sum0 += __shfl_xor_sync(0xffffffffu, sum0, 1);
        sum0 += __shfl_xor_sync(0xffffffffu, sum0, 2);
        sum1 += __shfl_xor_sync(0xffffffffu, sum1, 1);
        sum1 += __shfl_xor_sync(0xffffffffu, sum1, 2);
        l0 = l0 * a0 + sum0; l1 = l1 * a1 + sum1;
        m0 = mn0; m1 = mn1;
#pragma unroll
        for (int nb = 0; nb < 16; nb++) {
            o[nb][0] *= a0; o[nb][1] *= a0;
            o[nb][2] *= a1; o[nb][3] *= a1;
        }

#pragma unroll
        for (int kk = 0; kk < 4; kk++) {
            uint32_t pah[4], pal[4];
            split2(s[2 * kk][0],     s[2 * kk][1],     pah[0], pal[0]);
            split2(s[2 * kk][2],     s[2 * kk][3],     pah[1], pal[1]);
            split2(s[2 * kk + 1][0], s[2 * kk + 1][1], pah[2], pal[2]);
            split2(s[2 * kk + 1][2], s[2 * kk + 1][3], pah[3], pal[3]);
#pragma unroll
            for (int blk = 0; blk < 8; blk++) {
                uint32_t vb[4], vl[4];
                uint32_t va = sb + SM_VH + ((blk * 16 + lrow) * VSTR + kk * 16 + lcol8) * 2;
                uint32_t va2 = sb + SM_VL + ((blk * 16 + lrow) * VSTR + kk * 16 + lcol8) * 2;
                ldm_x4(vb, va);
                ldm_x4(vl, va2);
                mma16816(o[2 * blk + 0], pah, vb[0], vb[2]);
                mma16816(o[2 * blk + 1], pah, vb[1], vb[3]);
                mma16816(o[2 * blk + 0], pah, vl[0], vl[2]);
                mma16816(o[2 * blk + 1], pah, vl[1], vl[3]);
                mma16816(o[2 * blk + 0], pal, vb[0], vb[2]);
                mma16816(o[2 * blk + 1], pal, vb[1], vb[3]);
            }
        }
        __syncthreads();
    }

    float inv0 = 1.0f / l0, inv1 = 1.0f / l1;
    int b = bh >> 4, h = bh & 15;
    int r0 = qb * ABM + wid * 16 + qrow;
    float* base0 = g_ctx + ((size_t)(b * TSEQ + r0)) * DM + h * HD + qcol;
    float* base1 = g_ctx + ((size_t)(b * TSEQ + r0 + 8)) * DM + h * HD + qcol;
#pragma unroll
    for (int nb = 0; nb < 16; nb++) {
        *(float2*)(base0 + nb * 8) = make_float2(o[nb][0] * inv0, o[nb][1] * inv0);
        *(float2*)(base1 + nb * 8) = make_float2(o[nb][2] * inv1, o[nb][3] * inv1);
    }
}

// ---------------- launcher --------------------------------------------------------
extern "C" void kernel_launch(void* const* d_in, const int* in_sizes, int n_in,
                              void* d_out, int out_size) {
    const float* x    = (const float*)d_in[0];
    const float* Wqkv = (const float*)d_in[1];
    const float* bqkv = (const float*)d_in[2];
    const float* Wo   = (const float*)d_in[3];
    const float* bo   = (const float*)d_in[4];
    float* out = (float*)d_out;

    float *qkv_p, *ctx_p;
    cudaGetSymbolAddress((void**)&qkv_p, g_qkv);
    cudaGetSymbolAddress((void**)&ctx_p, g_ctx);
    __half *xh, *wqh, *wql, *woh, *wol, *ch;
    cudaGetSymbolAddress((void**)&xh, g_xh);
    cudaGetSymbolAddress((void**)&wqh, g_wqkvh);
    cudaGetSymbolAddress((void**)&wql, g_wqkvl);
    cudaGetSymbolAddress((void**)&woh, g_woh);
    cudaGetSymbolAddress((void**)&wol, g_wol);
    cudaGetSymbolAddress((void**)&ch, g_ch);

    cudaFuncSetAttribute(gemm_fp16_2t,
                         cudaFuncAttributeMaxDynamicSharedMemorySize, G_SMEM_TOTAL);
    cudaFuncSetAttribute(attn_mma_kernel,
                         cudaFuncAttributeMaxDynamicSharedMemorySize, ATT_SMEM);

    // 1) RoPE table
    rope_table_kernel<<<(TSEQ * (HD / 2) + 255) / 256, 256>>>();

    // 2) converts: x -> fp16 hi; Wqkv -> fp16 hi/lo
    {
        int n2 = (NTOK * DM) / 2;
        convert_hi_fp16<<<(n2 + 255) / 256, 256>>>((const float2*)x, (__half2*)xh, n2);
        n2 = (QKV_COLS * DM) / 2;
        convert_split_fp16<<<(n2 + 255) / 256, 256>>>((const float2*)Wqkv,
            (__half2*)wqh, (__half2*)wql, n2);
    }

    // 3) QKV projection (fp16 2-term HMMA)
    {
        dim3 grid(QKV_COLS / 128, NTOK / 128);
        gemm_fp16_2t<<<grid, 256, G_SMEM_TOTAL>>>(xh, wqh, wql, bqkv, qkv_p,
                                                  NTOK, QKV_COLS, DM);
    }

    // 4) RoPE + head split + bf16 split + V transpose
    {
        dim3 grid(NTOK, NH);
        rope_split_kernel<<<grid, HD>>>();
    }

    // 5) causal flash attention (bf16x3 HMMA)
    {
        dim3 grid(TSEQ / ABM, BB * NH);
        attn_mma_kernel<<<grid, 256, ATT_SMEM>>>();
    }

    // 6) converts: ctx -> fp16 hi; Wo -> fp16 hi/lo
    {
        int n2 = (NTOK * DM) / 2;
        convert_hi_fp16<<<(n2 + 255) / 256, 256>>>((const float2*)ctx_p, (__half2*)ch, n2);
        n2 = (DM * DM) / 2;
        convert_split_fp16<<<(n2 + 255) / 256, 256>>>((const float2*)Wo,
            (__half2*)woh, (__half2*)wol, n2);
    }

    // 7) output projection (fp16 2-term HMMA)
    {
        dim3 grid(DM / 128, NTOK / 128);
        gemm_fp16_2t<<<grid, 256, G_SMEM_TOTAL>>>(ch, woh, wol, bo, out,
                                                  NTOK, DM, DM);
    }
}

// round 6
// speedup vs baseline: 3.9646x; 1.1067x over previous
#include <cuda_runtime.h>
#include <cuda_fp16.h>
#include <math.h>
#include <stdint.h>

#define NH 16
#define HD 128
#define TSEQ 2048
#define BB 2
#define DM 2048
#define NTOK (BB * TSEQ)          // 4096
#define QKV_COLS (3 * DM)         // 6144

// ---------------- scratch (device globals: no allocation allowed) ------------
__device__ float g_qkv[(size_t)NTOK * QKV_COLS];
__device__ float g_ctx[(size_t)NTOK * DM];
__device__ float g_cos[TSEQ * (HD / 2)];
__device__ float g_sin[TSEQ * (HD / 2)];
// fp16 operands for projections (A: hi only; B: hi+lo)
__device__ __half g_xh[(size_t)NTOK * DM];
__device__ __half g_wqkvh[(size_t)QKV_COLS * DM];
__device__ __half g_wqkvl[(size_t)QKV_COLS * DM];
__device__ __half g_woh[(size_t)DM * DM];
__device__ __half g_wol[(size_t)DM * DM];
__device__ __half g_ch[(size_t)NTOK * DM];
// attention operands (fp16). q: hi; k: hi/lo; vt: hi, [BH][HD][T]
#define BH_T_HD ((size_t)BB * NH * TSEQ * HD)
__device__ __half g_qh[BH_T_HD];
__device__ __half g_kh[BH_T_HD];
__device__ __half g_kl[BH_T_HD];
__device__ __half g_vth[BH_T_HD];

// ---------------- helpers ------------------------------------------------------
__device__ __forceinline__ uint32_t smem_u32(const void* p) {
    uint32_t a;
    asm("{ .reg .u64 t; cvta.to.shared.u64 t, %1; cvt.u32.u64 %0, t; }"
        : "=r"(a) : "l"(p));
    return a;
}
__device__ __forceinline__ void cpa16(uint32_t dst, const void* src) {
    asm volatile("cp.async.cg.shared.global [%0], [%1], 16;" :: "r"(dst), "l"(src));
}
__device__ __forceinline__ void ldm_x4(uint32_t* r, uint32_t addr) {
    asm volatile("ldmatrix.sync.aligned.m8n8.x4.shared.b16 {%0,%1,%2,%3}, [%4];"
                 : "=r"(r[0]), "=r"(r[1]), "=r"(r[2]), "=r"(r[3]) : "r"(addr));
}
__device__ __forceinline__ void mma16816h(float* d, const uint32_t* a, uint32_t b0, uint32_t b1) {
    asm volatile(
        "mma.sync.aligned.m16n8k16.row.col.f32.f16.f16.f32 "
        "{%0,%1,%2,%3}, {%4,%5,%6,%7}, {%8,%9}, {%0,%1,%2,%3};"
        : "+f"(d[0]), "+f"(d[1]), "+f"(d[2]), "+f"(d[3])
        : "r"(a[0]), "r"(a[1]), "r"(a[2]), "r"(a[3]), "r"(b0), "r"(b1));
}
// pack two fp32 -> f16x2 (p0 in low half)
__device__ __forceinline__ uint32_t packh(float p0, float p1) {
    uint32_t r;
    asm("cvt.rn.f16x2.f32 %0, %1, %2;" : "=r"(r) : "f"(p1), "f"(p0));
    return r;
}
// hi/lo fp16 split of a fp32 pair
__device__ __forceinline__ void split2h(float p0, float p1, uint32_t& ph, uint32_t& pl) {
    __half h0 = __float2half_rn(p0);
    __half h1 = __float2half_rn(p1);
    ph = ((uint32_t)__half_as_ushort(h1) << 16) | __half_as_ushort(h0);
    pl = packh(p0 - __half2float(h0), p1 - __half2float(h1));
}

// ---------------- RoPE table ----------------------------------------------------
__global__ void rope_table_kernel() {
    int idx = blockIdx.x * blockDim.x + threadIdx.x;
    if (idx >= TSEQ * (HD / 2)) return;
    int t = idx / (HD / 2);
    int i = idx % (HD / 2);
    double inv = exp(-log(10000.0) * (double)(2 * i) / (double)HD);
    double ang = (double)t * inv;
    g_cos[idx] = (float)cos(ang);
    g_sin[idx] = (float)sin(ang);
}

// ---------------- fp32 -> fp16 converts ------------------------------------------
__global__ void convert_hi_fp16(const float2* __restrict__ s, __half2* __restrict__ hi, int n2) {
    int i = blockIdx.x * 256 + threadIdx.x;
    if (i >= n2) return;
    float2 v = s[i];
    hi[i] = __floats2half2_rn(v.x, v.y);
}
__global__ void convert_split_fp16(const float2* __restrict__ s,
                                   __half2* __restrict__ hi,
                                   __half2* __restrict__ lo, int n2) {
    int i = blockIdx.x * 256 + threadIdx.x;
    if (i >= n2) return;
    float2 v = s[i];
    __half h0 = __float2half_rn(v.x);
    __half h1 = __float2half_rn(v.y);
    hi[i] = __halves2half2(h0, h1);
    lo[i] = __floats2half2_rn(v.x - __half2float(h0), v.y - __half2float(h1));
}

// ---------------- RoPE + head split + fp16 + tiled V transpose -------------------
// grid: (TSEQ/32, NH, BB), 256 threads. 32-token x 128-d tile per block.
__global__ void __launch_bounds__(256)
rope_split2_kernel() {
    __shared__ __half vsm[128 * 40];    // [d][t], stride 40 for aligned 16B rows
    int t0 = blockIdx.x * 32;
    int h = blockIdx.y;
    int b = blockIdx.z;
    int tid = threadIdx.x;
    int tt = tid >> 3;                  // token within tile (0..31)
    int pb = (tid & 7) * 8;             // pair base (0..56)
    int t = t0 + tt;
    int bh = b * NH + h;
    const float* base = g_qkv + (size_t)(b * TSEQ + t) * QKV_COLS;

    union U8 { __half h[8]; uint4 u[1]; };
    U8 qo1, qo2, kh1, kh2, kl1, kl2;
#pragma unroll
    for (int j = 0; j < 8; j++) {
        int d = pb + j;
        float c = g_cos[t * 64 + d];
        float s = g_sin[t * 64 + d];
        float q1 = base[h * HD + d];
        float q2 = base[h * HD + d + 64];
        float k1 = base[DM + h * HD + d];
        float k2 = base[DM + h * HD + d + 64];
        float qa = (q1 * c - q2 * s) * 0.08838834764831845f;
        float qb = (q1 * s + q2 * c) * 0.08838834764831845f;
        float ka = k1 * c - k2 * s;
        float kb = k1 * s + k2 * c;
        qo1.h[j] = __float2half_rn(qa);
        qo2.h[j] = __float2half_rn(qb);
        kh1.h[j] = __float2half_rn(ka);
        kl1.h[j] = __float2half_rn(ka - __half2float(kh1.h[j]));
        kh2.h[j] = __float2half_rn(kb);
        kl2.h[j] = __float2half_rn(kb - __half2float(kh2.h[j]));
        float v1 = base[2 * DM + h * HD + d];
        float v2 = base[2 * DM + h * HD + d + 64];
        vsm[d * 40 + tt] = __float2half_rn(v1);
        vsm[(d + 64) * 40 + tt] = __float2half_rn(v2);
    }
    size_t o = ((size_t)bh * TSEQ + t) * HD + pb;
    *(uint4*)(g_qh + o)      = qo1.u[0];
    *(uint4*)(g_qh + o + 64) = qo2.u[0];
    *(uint4*)(g_kh + o)      = kh1.u[0];
    *(uint4*)(g_kh + o + 64) = kh2.u[0];
    *(uint4*)(g_kl + o)      = kl1.u[0];
    *(uint4*)(g_kl + o + 64) = kl2.u[0];
    __syncthreads();

    // write transposed V: thread -> (d, 16-token half), 32B contiguous stores
    int d = tid >> 1, th = (tid & 1) * 16;
    uint4 a = *(uint4*)(vsm + d * 40 + th);
    uint4 b2 = *(uint4*)(vsm + d * 40 + th + 8);
    __half* dst = g_vth + ((size_t)bh * HD + d) * TSEQ + t0 + th;
    *(uint4*)(dst) = a;
    *(uint4*)(dst + 8) = b2;
}

// ---------------- HMMA fp16 2-term GEMM, 3-stage pipeline ------------------------
// C = Ah @ (Bh + Bl)^T + bias. 128x128x64 tile, 8 warps (4m x 2n), m16n8k16.
#define GROW 72                           // padded smem row (fp16 elems)
#define GTILE_B (128 * GROW * 2)          // 18432 bytes
#define GSTAGE_B (3 * GTILE_B)            // 55296 bytes (Ah, Bh, Bl)
#define G_SMEM_TOTAL (3 * GSTAGE_B)       // 165888 bytes, 3 stages

__device__ __forceinline__ void ld_tile64(uint32_t dst, const __half* g, int ldK) {
#pragma unroll
    for (int r = 0; r < 4; r++) {
        int idx = threadIdx.x + r * 256;
        int row = idx >> 3, c = idx & 7;
        cpa16(dst + (row * GROW + c * 8) * 2, g + (size_t)row * ldK + c * 8);
    }
}

__global__ void __launch_bounds__(256, 1)
gemm_fp16_2t(const __half* __restrict__ Ah,
             const __half* __restrict__ Bhi, const __half* __restrict__ Blo,
             const float* __restrict__ bias, float* __restrict__ C,
             int M, int N, int K) {
    extern __shared__ __align__(128) char sm[];
    uint32_t sb = smem_u32(sm);
    int tid = threadIdx.x, wid = tid >> 5, lane = tid & 31;
    int wm = wid & 3, wn = wid >> 2;
    int bm = blockIdx.y * 128, bn = blockIdx.x * 128;

    const __half* Ap = Ah  + (size_t)bm * K;
    const __half* Bh = Bhi + (size_t)bn * K;
    const __half* Bl = Blo + (size_t)bn * K;

    float acc[2][8][4];
#pragma unroll
    for (int i = 0; i < 2; i++)
#pragma unroll
        for (int j = 0; j < 8; j++)
#pragma unroll
            for (int k = 0; k < 4; k++) acc[i][j][k] = 0.f;

    int nc = K / 64;
#pragma unroll
    for (int s = 0; s < 2; s++) {
        uint32_t st = sb + s * GSTAGE_B;
        ld_tile64(st + 0 * GTILE_B, Ap + s * 64, K);
        ld_tile64(st + 1 * GTILE_B, Bh + s * 64, K);
        ld_tile64(st + 2 * GTILE_B, Bl + s * 64, K);
        asm volatile("cp.async.commit_group;" ::: "memory");
    }

    int lrow = lane & 15;
    int lcol8 = (lane >> 4) * 8;

    for (int i = 0; i < nc; i++) {
        if (i == nc - 1) asm volatile("cp.async.wait_group 0;" ::: "memory");
        else             asm volatile("cp.async.wait_group 1;" ::: "memory");
        __syncthreads();

        // prefetch stage i+2 into the stage nobody reads this iteration
        if (i + 2 < nc) {
            uint32_t pf = sb + (uint32_t)((i + 2) % 3) * GSTAGE_B;
            int k0 = (i + 2) * 64;
            ld_tile64(pf + 0 * GTILE_B, Ap + k0, K);
            ld_tile64(pf + 1 * GTILE_B, Bh + k0, K);
            ld_tile64(pf + 2 * GTILE_B, Bl + k0, K);
            asm volatile("cp.async.commit_group;" ::: "memory");
        }

        uint32_t st = sb + (uint32_t)(i % 3) * GSTAGE_B;
        uint32_t sA = st, sBh = st + GTILE_B, sBl = st + 2 * GTILE_B;

#pragma unroll
        for (int ks = 0; ks < 4; ks++) {
            int kc = ks * 16 + lcol8;
            uint32_t a[2][4], bh[4][4], bl[4][4];
#pragma unroll
            for (int mi = 0; mi < 2; mi++) {
                int r = wm * 32 + mi * 16 + lrow;
                ldm_x4(a[mi], sA + (r * GROW + kc) * 2);
            }
#pragma unroll
            for (int nb = 0; nb < 4; nb++) {
                int r = wn * 64 + nb * 16 + lrow;
                ldm_x4(bh[nb], sBh + (r * GROW + kc) * 2);
                ldm_x4(bl[nb], sBl + (r * GROW + kc) * 2);
            }
#pragma unroll
            for (int mi = 0; mi < 2; mi++)
#pragma unroll
                for (int nb = 0; nb < 4; nb++) {
                    mma16816h(acc[mi][2 * nb + 0], a[mi], bh[nb][0], bh[nb][2]);
                    mma16816h(acc[mi][2 * nb + 1], a[mi], bh[nb][1], bh[nb][3]);
                    mma16816h(acc[mi][2 * nb + 0], a[mi], bl[nb][0], bl[nb][2]);
                    mma16816h(acc[mi][2 * nb + 1], a[mi], bl[nb][1], bl[nb][3]);
                }
        }
    }

    int qrow = lane >> 2, qcol = (lane & 3) * 2;
#pragma unroll
    for (int mi = 0; mi < 2; mi++) {
#pragma unroll
        for (int ni = 0; ni < 8; ni++) {
            int c = bn + wn * 64 + ni * 8 + qcol;
            float b0 = bias[c], b1 = bias[c + 1];
            int r0 = bm + wm * 32 + mi * 16 + qrow;
            float2 v0 = make_float2(acc[mi][ni][0] + b0, acc[mi][ni][1] + b1);
            float2 v1 = make_float2(acc[mi][ni][2] + b0, acc[mi][ni][3] + b1);
            *(float2*)(C + (size_t)r0 * N + c) = v0;
            *(float2*)(C + (size_t)(r0 + 8) * N + c) = v1;
        }
    }
}

// ---------------- HMMA flash attention (causal), fp16 2-term ---------------------
// CTA: 128 q-rows x 64-key tiles; 8 warps, each one m16 slice, full N=64.
#define ABM 128
#define ABN 64
#define QSTR 136
#define KSTR 136
#define VSTR 72
#define SM_Q  0
#define SM_KH (SM_Q + ABM * QSTR * 2)           // 34816
#define SM_KL (SM_KH + ABN * KSTR * 2)          // 52224
#define SM_V  (SM_KL + ABN * KSTR * 2)          // 69632
#define ATT_SMEM (SM_V + HD * VSTR * 2)         // 88064

__global__ void __launch_bounds__(256, 2)
attn_mma_kernel() {
    extern __shared__ __align__(128) char smA[];
    uint32_t sb = smem_u32(smA);
    int tid = threadIdx.x, wid = tid >> 5, lane = tid & 31;
    int qb = blockIdx.x;
    int bh = blockIdx.y;
    int lrow = lane & 15;
    int lcol8 = (lane >> 4) * 8;
    int qrow = lane >> 2, qcol = (lane & 3) * 2;

    // ---- load Q tile (fp16 hi) ----
    {
        const __half* Q = g_qh + ((size_t)bh * TSEQ + qb * ABM) * HD;
#pragma unroll
        for (int i = 0; i < 8; i++) {
            int idx = tid + i * 256;
            int row = idx >> 4, c = idx & 15;
            cpa16(sb + SM_Q + (row * QSTR + c * 8) * 2, Q + (size_t)row * HD + c * 8);
        }
        asm volatile("cp.async.commit_group;" ::: "memory");
        asm volatile("cp.async.wait_group 0;" ::: "memory");
        __syncthreads();
    }

    float o[16][4];
#pragma unroll
    for (int i = 0; i < 16; i++)
#pragma unroll
        for (int j = 0; j < 4; j++) o[i][j] = 0.f;
    float m0 = -1e30f, m1 = -1e30f, l0 = 0.f, l1 = 0.f;

    int nkb = 2 * qb + 2;
    for (int kb = 0; kb < nkb; kb++) {
        // ---- load K (hi/lo) and V (hi, transposed) tiles ----
        {
            const __half* Kh = g_kh + ((size_t)bh * TSEQ + kb * ABN) * HD;
            const __half* Kl = g_kl + ((size_t)bh * TSEQ + kb * ABN) * HD;
#pragma unroll
            for (int i = 0; i < 4; i++) {
                int idx = tid + i * 256;
                int row = idx >> 4, c = idx & 15;
                cpa16(sb + SM_KH + (row * KSTR + c * 8) * 2, Kh + (size_t)row * HD + c * 8);
                cpa16(sb + SM_KL + (row * KSTR + c * 8) * 2, Kl + (size_t)row * HD + c * 8);
            }
            const __half* V = g_vth + (size_t)bh * HD * TSEQ + kb * ABN;
#pragma unroll
            for (int i = 0; i < 4; i++) {
                int idx = tid + i * 256;
                int row = idx >> 3, c = idx & 7;
                cpa16(sb + SM_V + (row * VSTR + c * 8) * 2, V + (size_t)row * TSEQ + c * 8);
            }
            asm volatile("cp.async.commit_group;" ::: "memory");
            asm volatile("cp.async.wait_group 0;" ::: "memory");
            __syncthreads();
        }

        // ---- S = Q K^T (Q hi-only, K 2-term) ----
        float s[8][4];
#pragma unroll
        for (int i = 0; i < 8; i++)
#pragma unroll
            for (int j = 0; j < 4; j++) s[i][j] = 0.f;
#pragma unroll
        for (int kc = 0; kc < 8; kc++) {
            uint32_t a[4];
            ldm_x4(a, sb + SM_Q + ((wid * 16 + lrow) * QSTR + kc * 16 + lcol8) * 2);
#pragma unroll
            for (int nb = 0; nb < 4; nb++) {
                uint32_t bhh[4], bll[4];
                ldm_x4(bhh, sb + SM_KH + ((nb * 16 + lrow) * KSTR + kc * 16 + lcol8) * 2);
                ldm_x4(bll, sb + SM_KL + ((nb * 16 + lrow) * KSTR + kc * 16 + lcol8) * 2);
                mma16816h(s[2 * nb + 0], a, bhh[0], bhh[2]);
                mma16816h(s[2 * nb + 1], a, bhh[1], bhh[3]);
                mma16816h(s[2 * nb + 0], a, bll[0], bll[2]);
                mma16816h(s[2 * nb + 1], a, bll[1], bll[3]);
            }
        }

        // ---- causal mask ----
        if (kb >= 2 * qb) {
            int rg = qb * ABM + wid * 16 + qrow;
#pragma unroll
            for (int nb = 0; nb < 8; nb++) {
#pragma unroll
                for (int e = 0; e < 2; e++) {
                    int col = kb * ABN + nb * 8 + qcol + e;
                    if (col > rg)     s[nb][e]     = -1e30f;
                    if (col > rg + 8) s[nb][2 + e] = -1e30f;
                }
            }
        }

        // ---- online softmax ----
        float mx0 = -1e30f, mx1 = -1e30f;
#pragma unroll
        for (int nb = 0; nb < 8; nb++) {
            mx0 = fmaxf(mx0, fmaxf(s[nb][0], s[nb][1]));
            mx1 = fmaxf(mx1, fmaxf(s[nb][2], s[nb][3]));
        }
        mx0 = fmaxf(mx0, __shfl_xor_sync(0xffffffffu, mx0, 1));
        mx0 = fmaxf(mx0, __shfl_xor_sync(0xffffffffu, mx0, 2));
        mx1 = fmaxf(mx1, __shfl_xor_sync(0xffffffffu, mx1, 1));
        mx1 = fmaxf(mx1, __shfl_xor_sync(0xffffffffu, mx1, 2));
        float mn0 = fmaxf(m0, mx0), mn1 = fmaxf(m1, mx1);
        float a0 = __expf(m0 - mn0), a1 = __expf(m1 - mn1);
        float sum0 = 0.f, sum1 = 0.f;
#pragma unroll
        for (int nb = 0; nb < 8; nb++) {
            s[nb][0] = __expf(s[nb][0] - mn0); sum0 += s[nb][0];
            s[nb][1] = __expf(s[nb][1] - mn0); sum0 += s[nb][1];
            s[nb][2] = __expf(s[nb][2] - mn1); sum1 += s[nb][2];
            s[nb][3] = __expf(s[nb][3] - mn1); sum1 += s[nb][3];
        }
        sum0 += __shfl_xor_sync(0xffffffffu, sum0, 1);
        sum0 += __shfl_xor_sync(0xffffffffu, sum0, 2);
        sum1 += __shfl_xor_sync(0xffffffffu, sum1, 1);
        sum1 += __shfl_xor_sync(0xffffffffu, sum1, 2);
        l0 = l0 * a0 + sum0; l1 = l1 * a1 + sum1;
        m0 = mn0; m1 = mn1;
#pragma unroll
        for (int nb = 0; nb < 16; nb++) {
            o[nb][0] *= a0; o[nb][1] *= a0;
            o[nb][2] *= a1; o[nb][3] *= a1;
        }

        // ---- O += P @ V (P 2-term fp16, V hi-only) ----
#pragma unroll
        for (int kk = 0; kk < 4; kk++) {
            uint32_t pah[4], pal[4];
            split2h(s[2 * kk][0],     s[2 * kk][1],     pah[0], pal[0]);
            split2h(s[2 * kk][2],     s[2 * kk][3],     pah[1], pal[1]);
            split2h(s[2 * kk + 1][0], s[2 * kk + 1][1], pah[2], pal[2]);
            split2h(s[2 * kk + 1][2], s[2 * kk + 1][3], pah[3], pal[3]);
#pragma unroll
            for (int blk = 0; blk < 8; blk++) {
                uint32_t vb[4];
                ldm_x4(vb, sb + SM_V + ((blk * 16 + lrow) * VSTR + kk * 16 + lcol8) * 2);
                mma16816h(o[2 * blk + 0], pah, vb[0], vb[2]);
                mma16816h(o[2 * blk + 1], pah, vb[1], vb[3]);
                mma16816h(o[2 * blk + 0], pal, vb[0], vb[2]);
                mma16816h(o[2 * blk + 1], pal, vb[1], vb[3]);
            }
        }
        __syncthreads();   // before next kb overwrites K/V smem
    }

    // ---- epilogue ----
    float inv0 = 1.0f / l0, inv1 = 1.0f / l1;
    int b = bh >> 4, h = bh & 15;
    int r0 = qb * ABM + wid * 16 + qrow;
    float* base0 = g_ctx + ((size_t)(b * TSEQ + r0)) * DM + h * HD + qcol;
    float* base1 = g_ctx + ((size_t)(b * TSEQ + r0 + 8)) * DM + h * HD + qcol;
#pragma unroll
    for (int nb = 0; nb < 16; nb++) {
        *(float2*)(base0 + nb * 8) = make_float2(o[nb][0] * inv0, o[nb][1] * inv0);
        *(float2*)(base1 + nb * 8) = make_float2(o[nb][2] * inv1, o[nb][3] * inv1);
    }
}

// ---------------- launcher --------------------------------------------------------
extern "C" void kernel_launch(void* const* d_in, const int* in_sizes, int n_in,
                              void* d_out, int out_size) {
    const float* x    = (const float*)d_in[0];
    const float* Wqkv = (const float*)d_in[1];
    const float* bqkv = (const float*)d_in[2];
    const float* Wo   = (const float*)d_in[3];
    const float* bo   = (const float*)d_in[4];
    float* out = (float*)d_out;

    float *qkv_p, *ctx_p;
    cudaGetSymbolAddress((void**)&qkv_p, g_qkv);
    cudaGetSymbolAddress((void**)&ctx_p, g_ctx);
    __half *xh, *wqh, *wql, *woh, *wol, *ch;
    cudaGetSymbolAddress((void**)&xh, g_xh);
    cudaGetSymbolAddress((void**)&wqh, g_wqkvh);
    cudaGetSymbolAddress((void**)&wql, g_wqkvl);
    cudaGetSymbolAddress((void**)&woh, g_woh);
    cudaGetSymbolAddress((void**)&wol, g_wol);
    cudaGetSymbolAddress((void**)&ch, g_ch);

    cudaFuncSetAttribute(gemm_fp16_2t,
                         cudaFuncAttributeMaxDynamicSharedMemorySize, G_SMEM_TOTAL);
    cudaFuncSetAttribute(attn_mma_kernel,
                         cudaFuncAttributeMaxDynamicSharedMemorySize, ATT_SMEM);

    // 1) RoPE table
    rope_table_kernel<<<(TSEQ * (HD / 2) + 255) / 256, 256>>>();

    // 2) converts: x -> fp16 hi; Wqkv -> fp16 hi/lo
    {
        int n2 = (NTOK * DM) / 2;
        convert_hi_fp16<<<(n2 + 255) / 256, 256>>>((const float2*)x, (__half2*)xh, n2);
        n2 = (QKV_COLS * DM) / 2;
        convert_split_fp16<<<(n2 + 255) / 256, 256>>>((const float2*)Wqkv,
            (__half2*)wqh, (__half2*)wql, n2);
    }

    // 3) QKV projection (fp16 2-term HMMA, 3-stage)
    {
        dim3 grid(QKV_COLS / 128, NTOK / 128);
        gemm_fp16_2t<<<grid, 256, G_SMEM_TOTAL>>>(xh, wqh, wql, bqkv, qkv_p,
                                                  NTOK, QKV_COLS, DM);
    }

    // 4) RoPE + head split + fp16 + tiled V transpose
    {
        dim3 grid(TSEQ / 32, NH, BB);
        rope_split2_kernel<<<grid, 256>>>();
    }

    // 5) causal flash attention (fp16 2-term HMMA)
    {
        dim3 grid(TSEQ / ABM, BB * NH);
        attn_mma_kernel<<<grid, 256, ATT_SMEM>>>();
    }

    // 6) converts: ctx -> fp16 hi; Wo -> fp16 hi/lo
    {
        int n2 = (NTOK * DM) / 2;
        convert_hi_fp16<<<(n2 + 255) / 256, 256>>>((const float2*)ctx_p, (__half2*)ch, n2);
        n2 = (DM * DM) / 2;
        convert_split_fp16<<<(n2 + 255) / 256, 256>>>((const float2*)Wo,
            (__half2*)woh, (__half2*)wol, n2);
    }

    // 7) output projection (fp16 2-term HMMA, 3-stage)
    {
        dim3 grid(DM / 128, NTOK / 128);
        gemm_fp16_2t<<<grid, 256, G_SMEM_TOTAL>>>(ch, woh, wol, bo, out,
                                                  NTOK, DM, DM);
    }
}

// round 7
// speedup vs baseline: 4.0041x; 1.0100x over previous
#include <cuda_runtime.h>
#include <cuda_fp16.h>
#include <math.h>
#include <stdint.h>

#define NH 16
#define HD 128
#define TSEQ 2048
#define BB 2
#define DM 2048
#define NTOK (BB * TSEQ)          // 4096
#define QKV_COLS (3 * DM)         // 6144

// ---------------- scratch (device globals: no allocation allowed) ------------
__device__ float g_qkv[(size_t)NTOK * QKV_COLS];
__device__ float g_ctx[(size_t)NTOK * DM];
__device__ float g_cos[TSEQ * (HD / 2)];
__device__ float g_sin[TSEQ * (HD / 2)];
// fp16 operands for projections (A: hi only; B: hi+lo)
__device__ __half g_xh[(size_t)NTOK * DM];
__device__ __half g_wqkvh[(size_t)QKV_COLS * DM];
__device__ __half g_wqkvl[(size_t)QKV_COLS * DM];
__device__ __half g_woh[(size_t)DM * DM];
__device__ __half g_wol[(size_t)DM * DM];
__device__ __half g_ch[(size_t)NTOK * DM];
// attention operands (fp16). q: hi; k: hi/lo; vt: hi, [BH][HD][T]
#define BH_T_HD ((size_t)BB * NH * TSEQ * HD)
__device__ __half g_qh[BH_T_HD];
__device__ __half g_kh[BH_T_HD];
__device__ __half g_kl[BH_T_HD];
__device__ __half g_vth[BH_T_HD];

// ---------------- helpers ------------------------------------------------------
__device__ __forceinline__ uint32_t smem_u32(const void* p) {
    uint32_t a;
    asm("{ .reg .u64 t; cvta.to.shared.u64 t, %1; cvt.u32.u64 %0, t; }"
        : "=r"(a) : "l"(p));
    return a;
}
__device__ __forceinline__ void cpa16(uint32_t dst, const void* src) {
    asm volatile("cp.async.cg.shared.global [%0], [%1], 16;" :: "r"(dst), "l"(src));
}
__device__ __forceinline__ void ldm_x4(uint32_t* r, uint32_t addr) {
    asm volatile("ldmatrix.sync.aligned.m8n8.x4.shared.b16 {%0,%1,%2,%3}, [%4];"
                 : "=r"(r[0]), "=r"(r[1]), "=r"(r[2]), "=r"(r[3]) : "r"(addr));
}
__device__ __forceinline__ void mma16816h(float* d, const uint32_t* a, uint32_t b0, uint32_t b1) {
    asm volatile(
        "mma.sync.aligned.m16n8k16.row.col.f32.f16.f16.f32 "
        "{%0,%1,%2,%3}, {%4,%5,%6,%7}, {%8,%9}, {%0,%1,%2,%3};"
        : "+f"(d[0]), "+f"(d[1]), "+f"(d[2]), "+f"(d[3])
        : "r"(a[0]), "r"(a[1]), "r"(a[2]), "r"(a[3]), "r"(b0), "r"(b1));
}
__device__ __forceinline__ uint32_t packh(float p0, float p1) {
    uint32_t r;
    asm("cvt.rn.f16x2.f32 %0, %1, %2;" : "=r"(r) : "f"(p1), "f"(p0));
    return r;
}
__device__ __forceinline__ void split2h(float p0, float p1, uint32_t& ph, uint32_t& pl) {
    __half h0 = __float2half_rn(p0);
    __half h1 = __float2half_rn(p1);
    ph = ((uint32_t)__half_as_ushort(h1) << 16) | __half_as_ushort(h0);
    pl = packh(p0 - __half2float(h0), p1 - __half2float(h1));
}

// ---------------- RoPE table ----------------------------------------------------
__global__ void rope_table_kernel() {
    int idx = blockIdx.x * blockDim.x + threadIdx.x;
    if (idx >= TSEQ * (HD / 2)) return;
    int t = idx / (HD / 2);
    int i = idx % (HD / 2);
    double inv = exp(-log(10000.0) * (double)(2 * i) / (double)HD);
    double ang = (double)t * inv;
    g_cos[idx] = (float)cos(ang);
    g_sin[idx] = (float)sin(ang);
}

// ---------------- fp32 -> fp16 converts ------------------------------------------
__global__ void convert_hi_fp16(const float2* __restrict__ s, __half2* __restrict__ hi, int n2) {
    int i = blockIdx.x * 256 + threadIdx.x;
    if (i >= n2) return;
    float2 v = s[i];
    hi[i] = __floats2half2_rn(v.x, v.y);
}
__global__ void convert_split_fp16(const float2* __restrict__ s,
                                   __half2* __restrict__ hi,
                                   __half2* __restrict__ lo, int n2) {
    int i = blockIdx.x * 256 + threadIdx.x;
    if (i >= n2) return;
    float2 v = s[i];
    __half h0 = __float2half_rn(v.x);
    __half h1 = __float2half_rn(v.y);
    hi[i] = __halves2half2(h0, h1);
    lo[i] = __floats2half2_rn(v.x - __half2float(h0), v.y - __half2float(h1));
}

// ---------------- RoPE + head split + fp16 + tiled V transpose -------------------
__global__ void __launch_bounds__(256)
rope_split2_kernel() {
    __shared__ __half vsm[128 * 40];
    int t0 = blockIdx.x * 32;
    int h = blockIdx.y;
    int b = blockIdx.z;
    int tid = threadIdx.x;
    int tt = tid >> 3;
    int pb = (tid & 7) * 8;
    int t = t0 + tt;
    int bh = b * NH + h;
    const float* base = g_qkv + (size_t)(b * TSEQ + t) * QKV_COLS;

    union U8 { __half h[8]; uint4 u[1]; };
    U8 qo1, qo2, kh1, kh2, kl1, kl2;
#pragma unroll
    for (int j = 0; j < 8; j++) {
        int d = pb + j;
        float c = g_cos[t * 64 + d];
        float s = g_sin[t * 64 + d];
        float q1 = base[h * HD + d];
        float q2 = base[h * HD + d + 64];
        float k1 = base[DM + h * HD + d];
        float k2 = base[DM + h * HD + d + 64];
        float qa = (q1 * c - q2 * s) * 0.08838834764831845f;
        float qb = (q1 * s + q2 * c) * 0.08838834764831845f;
        float ka = k1 * c - k2 * s;
        float kb = k1 * s + k2 * c;
        qo1.h[j] = __float2half_rn(qa);
        qo2.h[j] = __float2half_rn(qb);
        kh1.h[j] = __float2half_rn(ka);
        kl1.h[j] = __float2half_rn(ka - __half2float(kh1.h[j]));
        kh2.h[j] = __float2half_rn(kb);
        kl2.h[j] = __float2half_rn(kb - __half2float(kh2.h[j]));
        float v1 = base[2 * DM + h * HD + d];
        float v2 = base[2 * DM + h * HD + d + 64];
        vsm[d * 40 + tt] = __float2half_rn(v1);
        vsm[(d + 64) * 40 + tt] = __float2half_rn(v2);
    }
    size_t o = ((size_t)bh * TSEQ + t) * HD + pb;
    *(uint4*)(g_qh + o)      = qo1.u[0];
    *(uint4*)(g_qh + o + 64) = qo2.u[0];
    *(uint4*)(g_kh + o)      = kh1.u[0];
    *(uint4*)(g_kh + o + 64) = kh2.u[0];
    *(uint4*)(g_kl + o)      = kl1.u[0];
    *(uint4*)(g_kl + o + 64) = kl2.u[0];
    __syncthreads();

    int d = tid >> 1, th = (tid & 1) * 16;
    uint4 a = *(uint4*)(vsm + d * 40 + th);
    uint4 b2 = *(uint4*)(vsm + d * 40 + th + 8);
    __half* dst = g_vth + ((size_t)bh * HD + d) * TSEQ + t0 + th;
    *(uint4*)(dst) = a;
    *(uint4*)(dst + 8) = b2;
}

// ---------------- HMMA fp16 2-term GEMM, 3-stage @ K-chunk 32, 2 CTA/SM ----------
// C = Ah @ (Bh + Bl)^T + bias. 128x128x32 tile, 8 warps (4m x 2n), m16n8k16.
#define GROW 40                           // padded smem row (fp16 elems)
#define GTILE_B (128 * GROW * 2)          // 10240 bytes
#define GSTAGE_B (3 * GTILE_B)            // 30720 bytes (Ah, Bh, Bl)
#define G_SMEM_TOTAL (3 * GSTAGE_B)       // 92160 bytes, 3 stages

// load one 128x32 fp16 tile (64B/row) into padded smem rows
__device__ __forceinline__ void ld_tile32(uint32_t dst, const __half* g, int ldK) {
#pragma unroll
    for (int r = 0; r < 2; r++) {
        int idx = threadIdx.x + r * 256;   // 512 chunks of 16B
        int row = idx >> 2, c = idx & 3;
        cpa16(dst + (row * GROW + c * 8) * 2, g + (size_t)row * ldK + c * 8);
    }
}

__global__ void __launch_bounds__(256, 2)
gemm_fp16_2t(const __half* __restrict__ Ah,
             const __half* __restrict__ Bhi, const __half* __restrict__ Blo,
             const float* __restrict__ bias, float* __restrict__ C,
             int M, int N, int K) {
    extern __shared__ __align__(128) char sm[];
    uint32_t sb = smem_u32(sm);
    int tid = threadIdx.x, wid = tid >> 5, lane = tid & 31;
    int wm = wid & 3, wn = wid >> 2;
    int bm = blockIdx.y * 128, bn = blockIdx.x * 128;

    const __half* Ap = Ah  + (size_t)bm * K;
    const __half* Bh = Bhi + (size_t)bn * K;
    const __half* Bl = Blo + (size_t)bn * K;

    float acc[2][8][4];
#pragma unroll
    for (int i = 0; i < 2; i++)
#pragma unroll
        for (int j = 0; j < 8; j++)
#pragma unroll
            for (int k = 0; k < 4; k++) acc[i][j][k] = 0.f;

    int nc = K / 32;
#pragma unroll
    for (int s = 0; s < 2; s++) {
        uint32_t st = sb + s * GSTAGE_B;
        ld_tile32(st + 0 * GTILE_B, Ap + s * 32, K);
        ld_tile32(st + 1 * GTILE_B, Bh + s * 32, K);
        ld_tile32(st + 2 * GTILE_B, Bl + s * 32, K);
        asm volatile("cp.async.commit_group;" ::: "memory");
    }

    int lrow = lane & 15;
    int lcol8 = (lane >> 4) * 8;

    for (int i = 0; i < nc; i++) {
        if (i == nc - 1) asm volatile("cp.async.wait_group 0;" ::: "memory");
        else             asm volatile("cp.async.wait_group 1;" ::: "memory");
        __syncthreads();

        // prefetch stage i+2 (nobody reads it this iteration)
        if (i + 2 < nc) {
            uint32_t pf = sb + (uint32_t)((i + 2) % 3) * GSTAGE_B;
            int k0 = (i + 2) * 32;
            ld_tile32(pf + 0 * GTILE_B, Ap + k0, K);
            ld_tile32(pf + 1 * GTILE_B, Bh + k0, K);
            ld_tile32(pf + 2 * GTILE_B, Bl + k0, K);
            asm volatile("cp.async.commit_group;" ::: "memory");
        }

        uint32_t st = sb + (uint32_t)(i % 3) * GSTAGE_B;
        uint32_t sA = st, sBh = st + GTILE_B, sBl = st + 2 * GTILE_B;

#pragma unroll
        for (int ks = 0; ks < 2; ks++) {
            int kc = ks * 16 + lcol8;
            uint32_t a[2][4], bh[4][4], bl[4][4];
#pragma unroll
            for (int mi = 0; mi < 2; mi++) {
                int r = wm * 32 + mi * 16 + lrow;
                ldm_x4(a[mi], sA + (r * GROW + kc) * 2);
            }
#pragma unroll
            for (int nb = 0; nb < 4; nb++) {
                int r = wn * 64 + nb * 16 + lrow;
                ldm_x4(bh[nb], sBh + (r * GROW + kc) * 2);
                ldm_x4(bl[nb], sBl + (r * GROW + kc) * 2);
            }
#pragma unroll
            for (int mi = 0; mi < 2; mi++)
#pragma unroll
                for (int nb = 0; nb < 4; nb++) {
                    mma16816h(acc[mi][2 * nb + 0], a[mi], bh[nb][0], bh[nb][2]);
                    mma16816h(acc[mi][2 * nb + 1], a[mi], bh[nb][1], bh[nb][3]);
                    mma16816h(acc[mi][2 * nb + 0], a[mi], bl[nb][0], bl[nb][2]);
                    mma16816h(acc[mi][2 * nb + 1], a[mi], bl[nb][1], bl[nb][3]);
                }
        }
    }

    int qrow = lane >> 2, qcol = (lane & 3) * 2;
#pragma unroll
    for (int mi = 0; mi < 2; mi++) {
#pragma unroll
        for (int ni = 0; ni < 8; ni++) {
            int c = bn + wn * 64 + ni * 8 + qcol;
            float b0 = bias[c], b1 = bias[c + 1];
            int r0 = bm + wm * 32 + mi * 16 + qrow;
            float2 v0 = make_float2(acc[mi][ni][0] + b0, acc[mi][ni][1] + b1);
            float2 v1 = make_float2(acc[mi][ni][2] + b0, acc[mi][ni][3] + b1);
            *(float2*)(C + (size_t)r0 * N + c) = v0;
            *(float2*)(C + (size_t)(r0 + 8) * N + c) = v1;
        }
    }
}

// ---------------- HMMA flash attention (causal), fp16 2-term ---------------------
#define ABM 128
#define ABN 64
#define QSTR 136
#define KSTR 136
#define VSTR 72
#define SM_Q  0
#define SM_KH (SM_Q + ABM * QSTR * 2)           // 34816
#define SM_KL (SM_KH + ABN * KSTR * 2)          // 52224
#define SM_V  (SM_KL + ABN * KSTR * 2)          // 69632
#define ATT_SMEM (SM_V + HD * VSTR * 2)         // 88064

__global__ void __launch_bounds__(256, 2)
attn_mma_kernel() {
    extern __shared__ __align__(128) char smA[];
    uint32_t sb = smem_u32(smA);
    int tid = threadIdx.x, wid = tid >> 5, lane = tid & 31;
    int qb = blockIdx.x;
    int bh = blockIdx.y;
    int lrow = lane & 15;
    int lcol8 = (lane >> 4) * 8;
    int qrow = lane >> 2, qcol = (lane & 3) * 2;

    {
        const __half* Q = g_qh + ((size_t)bh * TSEQ + qb * ABM) * HD;
#pragma unroll
        for (int i = 0; i < 8; i++) {
            int idx = tid + i * 256;
            int row = idx >> 4, c = idx & 15;
            cpa16(sb + SM_Q + (row * QSTR + c * 8) * 2, Q + (size_t)row * HD + c * 8);
        }
        asm volatile("cp.async.commit_group;" ::: "memory");
        asm volatile("cp.async.wait_group 0;" ::: "memory");
        __syncthreads();
    }

    float o[16][4];
#pragma unroll
    for (int i = 0; i < 16; i++)
#pragma unroll
        for (int j = 0; j < 4; j++) o[i][j] = 0.f;
    float m0 = -1e30f, m1 = -1e30f, l0 = 0.f, l1 = 0.f;

    int nkb = 2 * qb + 2;
    for (int kb = 0; kb < nkb; kb++) {
        {
            const __half* Kh = g_kh + ((size_t)bh * TSEQ + kb * ABN) * HD;
            const __half* Kl = g_kl + ((size_t)bh * TSEQ + kb * ABN) * HD;
#pragma unroll
            for (int i = 0; i < 4; i++) {
                int idx = tid + i * 256;
                int row = idx >> 4, c = idx & 15;
                cpa16(sb + SM_KH + (row * KSTR + c * 8) * 2, Kh + (size_t)row * HD + c * 8);
                cpa16(sb + SM_KL + (row * KSTR + c * 8) * 2, Kl + (size_t)row * HD + c * 8);
            }
            const __half* V = g_vth + (size_t)bh * HD * TSEQ + kb * ABN;
#pragma unroll
            for (int i = 0; i < 4; i++) {
                int idx = tid + i * 256;
                int row = idx >> 3, c = idx & 7;
                cpa16(sb + SM_V + (row * VSTR + c * 8) * 2, V + (size_t)row * TSEQ + c * 8);
            }
            asm volatile("cp.async.commit_group;" ::: "memory");
            asm volatile("cp.async.wait_group 0;" ::: "memory");
            __syncthreads();
        }

        float s[8][4];
#pragma unroll
        for (int i = 0; i < 8; i++)
#pragma unroll
            for (int j = 0; j < 4; j++) s[i][j] = 0.f;
#pragma unroll
        for (int kc = 0; kc < 8; kc++) {
            uint32_t a[4];
            ldm_x4(a, sb + SM_Q + ((wid * 16 + lrow) * QSTR + kc * 16 + lcol8) * 2);
#pragma unroll
            for (int nb = 0; nb < 4; nb++) {
                uint32_t bhh[4], bll[4];
                ldm_x4(bhh, sb + SM_KH + ((nb * 16 + lrow) * KSTR + kc * 16 + lcol8) * 2);
                ldm_x4(bll, sb + SM_KL + ((nb * 16 + lrow) * KSTR + kc * 16 + lcol8) * 2);
                mma16816h(s[2 * nb + 0], a, bhh[0], bhh[2]);
                mma16816h(s[2 * nb + 1], a, bhh[1], bhh[3]);
                mma16816h(s[2 * nb + 0], a, bll[0], bll[2]);
                mma16816h(s[2 * nb + 1], a, bll[1], bll[3]);
            }
        }

        if (kb >= 2 * qb) {
            int rg = qb * ABM + wid * 16 + qrow;
#pragma unroll
            for (int nb = 0; nb < 8; nb++) {
#pragma unroll
                for (int e = 0; e < 2; e++) {
                    int col = kb * ABN + nb * 8 + qcol + e;
                    if (col > rg)     s[nb][e]     = -1e30f;
                    if (col > rg + 8) s[nb][2 + e] = -1e30f;
                }
            }
        }

        float mx0 = -1e30f, mx1 = -1e30f;
#pragma unroll
        for (int nb = 0; nb < 8; nb++) {
            mx0 = fmaxf(mx0, fmaxf(s[nb][0], s[nb][1]));
            mx1 = fmaxf(mx1, fmaxf(s[nb][2], s[nb][3]));
        }
        mx0 = fmaxf(mx0, __shfl_xor_sync(0xffffffffu, mx0, 1));
        mx0 = fmaxf(mx0, __shfl_xor_sync(0xffffffffu, mx0, 2));
        mx1 = fmaxf(mx1, __shfl_xor_sync(0xffffffffu, mx1, 1));
        mx1 = fmaxf(mx1, __shfl_xor_sync(0xffffffffu, mx1, 2));
        float mn0 = fmaxf(m0, mx0), mn1 = fmaxf(m1, mx1);
        float a0 = __expf(m0 - mn0), a1 = __expf(m1 - mn1);
        float sum0 = 0.f, sum1 = 0.f;
#pragma unroll
        for (int nb = 0; nb < 8; nb++) {
            s[nb][0] = __expf(s[nb][0] - mn0); sum0 += s[nb][0];
            s[nb][1] = __expf(s[nb][1] - mn0); sum0 += s[nb][1];
            s[nb][2] = __expf(s[nb][2] - mn1); sum1 += s[nb][2];
            s[nb][3] = __expf(s[nb][3] - mn1); sum1 += s[nb][3];
        }
        sum0 += __shfl_xor_sync(0xffffffffu, sum0, 1);
        sum0 += __shfl_xor_sync(0xffffffffu, sum0, 2);
        sum1 += __shfl_xor_sync(0xffffffffu, sum1, 1);
        sum1 += __shfl_xor_sync(0xffffffffu, sum1, 2);
        l0 = l0 * a0 + sum0; l1 = l1 * a1 + sum1;
        m0 = mn0; m1 = mn1;
#pragma unroll
        for (int nb = 0; nb < 16; nb++) {
            o[nb][0] *= a0; o[nb][1] *= a0;
            o[nb][2] *= a1; o[nb][3] *= a1;
        }

#pragma unroll
        for (int kk = 0; kk < 4; kk++) {
            uint32_t pah[4], pal[4];
            split2h(s[2 * kk][0],     s[2 * kk][1],     pah[0], pal[0]);
            split2h(s[2 * kk][2],     s[2 * kk][3],     pah[1], pal[1]);
            split2h(s[2 * kk + 1][0], s[2 * kk + 1][1], pah[2], pal[2]);
            split2h(s[2 * kk + 1][2], s[2 * kk + 1][3], pah[3], pal[3]);
#pragma unroll
            for (int blk = 0; blk < 8; blk++) {
                uint32_t vb[4];
                ldm_x4(vb, sb + SM_V + ((blk * 16 + lrow) * VSTR + kk * 16 + lcol8) * 2);
                mma16816h(o[2 * blk + 0], pah, vb[0], vb[2]);
                mma16816h(o[2 * blk + 1], pah, vb[1], vb[3]);
                mma16816h(o[2 * blk + 0], pal, vb[0], vb[2]);
                mma16816h(o[2 * blk + 1], pal, vb[1], vb[3]);
            }
        }
        __syncthreads();
    }

    float inv0 = 1.0f / l0, inv1 = 1.0f / l1;
    int b = bh >> 4, h = bh & 15;
    int r0 = qb * ABM + wid * 16 + qrow;
    float* base0 = g_ctx + ((size_t)(b * TSEQ + r0)) * DM + h * HD + qcol;
    float* base1 = g_ctx + ((size_t)(b * TSEQ + r0 + 8)) * DM + h * HD + qcol;
#pragma unroll
    for (int nb = 0; nb < 16; nb++) {
        *(float2*)(base0 + nb * 8) = make_float2(o[nb][0] * inv0, o[nb][1] * inv0);
        *(float2*)(base1 + nb * 8) = make_float2(o[nb][2] * inv1, o[nb][3] * inv1);
    }
}

// ---------------- launcher --------------------------------------------------------
extern "C" void kernel_launch(void* const* d_in, const int* in_sizes, int n_in,
                              void* d_out, int out_size) {
    const float* x    = (const float*)d_in[0];
    const float* Wqkv = (const float*)d_in[1];
    const float* bqkv = (const float*)d_in[2];
    const float* Wo   = (const float*)d_in[3];
    const float* bo   = (const float*)d_in[4];
    float* out = (float*)d_out;

    float *qkv_p, *ctx_p;
    cudaGetSymbolAddress((void**)&qkv_p, g_qkv);
    cudaGetSymbolAddress((void**)&ctx_p, g_ctx);
    __half *xh, *wqh, *wql, *woh, *wol, *ch;
    cudaGetSymbolAddress((void**)&xh, g_xh);
    cudaGetSymbolAddress((void**)&wqh, g_wqkvh);
    cudaGetSymbolAddress((void**)&wql, g_wqkvl);
    cudaGetSymbolAddress((void**)&woh, g_woh);
    cudaGetSymbolAddress((void**)&wol, g_wol);
    cudaGetSymbolAddress((void**)&ch, g_ch);

    cudaFuncSetAttribute(gemm_fp16_2t,
                         cudaFuncAttributeMaxDynamicSharedMemorySize, G_SMEM_TOTAL);
    cudaFuncSetAttribute(attn_mma_kernel,
                         cudaFuncAttributeMaxDynamicSharedMemorySize, ATT_SMEM);

    // 1) RoPE table
    rope_table_kernel<<<(TSEQ * (HD / 2) + 255) / 256, 256>>>();

    // 2) converts: x -> fp16 hi; Wqkv -> fp16 hi/lo
    {
        int n2 = (NTOK * DM) / 2;
        convert_hi_fp16<<<(n2 + 255) / 256, 256>>>((const float2*)x, (__half2*)xh, n2);
        n2 = (QKV_COLS * DM) / 2;
        convert_split_fp16<<<(n2 + 255) / 256, 256>>>((const float2*)Wqkv,
            (__half2*)wqh, (__half2*)wql, n2);
    }

    // 3) QKV projection (fp16 2-term HMMA, 3-stage @ K32)
    {
        dim3 grid(QKV_COLS / 128, NTOK / 128);
        gemm_fp16_2t<<<grid, 256, G_SMEM_TOTAL>>>(xh, wqh, wql, bqkv, qkv_p,
                                                  NTOK, QKV_COLS, DM);
    }

    // 4) RoPE + head split + fp16 + tiled V transpose
    {
        dim3 grid(TSEQ / 32, NH, BB);
        rope_split2_kernel<<<grid, 256>>>();
    }

    // 5) causal flash attention (fp16 2-term HMMA)
    {
        dim3 grid(TSEQ / ABM, BB * NH);
        attn_mma_kernel<<<grid, 256, ATT_SMEM>>>();
    }

    // 6) converts: ctx -> fp16 hi; Wo -> fp16 hi/lo
    {
        int n2 = (NTOK * DM) / 2;
        convert_hi_fp16<<<(n2 + 255) / 256, 256>>>((const float2*)ctx_p, (__half2*)ch, n2);
        n2 = (DM * DM) / 2;
        convert_split_fp16<<<(n2 + 255) / 256, 256>>>((const float2*)Wo,
            (__half2*)woh, (__half2*)wol, n2);
    }

    // 7) output projection (fp16 2-term HMMA, 3-stage @ K32)
    {
        dim3 grid(DM / 128, NTOK / 128);
        gemm_fp16_2t<<<grid, 256, G_SMEM_TOTAL>>>(ch, woh, wol, bo, out,
                                                  NTOK, DM, DM);
    }
}

// round 8
// speedup vs baseline: 4.2205x; 1.0540x over previous
#include <cuda_runtime.h>
#include <cuda_fp16.h>
#include <math.h>
#include <stdint.h>

#define NH 16
#define HD 128
#define TSEQ 2048
#define BB 2
#define DM 2048
#define NTOK (BB * TSEQ)          // 4096
#define QKV_COLS (3 * DM)         // 6144

// ---------------- scratch (device globals: no allocation allowed) ------------
__device__ float g_qkv[(size_t)NTOK * QKV_COLS];
__device__ float g_ctx[(size_t)NTOK * DM];
__device__ float g_cos[TSEQ * (HD / 2)];
__device__ float g_sin[TSEQ * (HD / 2)];
// fp16 operands for projections (A: hi only; B: hi+lo)
__device__ __half g_xh[(size_t)NTOK * DM];
__device__ __half g_wqkvh[(size_t)QKV_COLS * DM];
__device__ __half g_wqkvl[(size_t)QKV_COLS * DM];
__device__ __half g_woh[(size_t)DM * DM];
__device__ __half g_wol[(size_t)DM * DM];
__device__ __half g_ch[(size_t)NTOK * DM];
// attention operands (fp16). q: hi; k: hi/lo; vt: hi, [BH][HD][T]
#define BH_T_HD ((size_t)BB * NH * TSEQ * HD)
__device__ __half g_qh[BH_T_HD];
__device__ __half g_kh[BH_T_HD];
__device__ __half g_kl[BH_T_HD];
__device__ __half g_vth[BH_T_HD];

// ---------------- helpers ------------------------------------------------------
__device__ __forceinline__ uint32_t smem_u32(const void* p) {
    uint32_t a;
    asm("{ .reg .u64 t; cvta.to.shared.u64 t, %1; cvt.u32.u64 %0, t; }"
        : "=r"(a) : "l"(p));
    return a;
}
__device__ __forceinline__ void cpa16(uint32_t dst, const void* src) {
    asm volatile("cp.async.cg.shared.global [%0], [%1], 16;" :: "r"(dst), "l"(src));
}
__device__ __forceinline__ void ldm_x4(uint32_t* r, uint32_t addr) {
    asm volatile("ldmatrix.sync.aligned.m8n8.x4.shared.b16 {%0,%1,%2,%3}, [%4];"
                 : "=r"(r[0]), "=r"(r[1]), "=r"(r[2]), "=r"(r[3]) : "r"(addr));
}
__device__ __forceinline__ void mma16816h(float* d, const uint32_t* a, uint32_t b0, uint32_t b1) {
    asm volatile(
        "mma.sync.aligned.m16n8k16.row.col.f32.f16.f16.f32 "
        "{%0,%1,%2,%3}, {%4,%5,%6,%7}, {%8,%9}, {%0,%1,%2,%3};"
        : "+f"(d[0]), "+f"(d[1]), "+f"(d[2]), "+f"(d[3])
        : "r"(a[0]), "r"(a[1]), "r"(a[2]), "r"(a[3]), "r"(b0), "r"(b1));
}
__device__ __forceinline__ uint32_t packh(float p0, float p1) {
    uint32_t r;
    asm("cvt.rn.f16x2.f32 %0, %1, %2;" : "=r"(r) : "f"(p1), "f"(p0));
    return r;
}
__device__ __forceinline__ void split2h(float p0, float p1, uint32_t& ph, uint32_t& pl) {
    __half h0 = __float2half_rn(p0);
    __half h1 = __float2half_rn(p1);
    ph = ((uint32_t)__half_as_ushort(h1) << 16) | __half_as_ushort(h0);
    pl = packh(p0 - __half2float(h0), p1 - __half2float(h1));
}

// ---------------- RoPE table ----------------------------------------------------
__global__ void rope_table_kernel() {
    int idx = blockIdx.x * blockDim.x + threadIdx.x;
    if (idx >= TSEQ * (HD / 2)) return;
    int t = idx / (HD / 2);
    int i = idx % (HD / 2);
    double inv = exp(-log(10000.0) * (double)(2 * i) / (double)HD);
    double ang = (double)t * inv;
    g_cos[idx] = (float)cos(ang);
    g_sin[idx] = (float)sin(ang);
}

// ---------------- fp32 -> fp16 converts ------------------------------------------
__global__ void convert_hi_fp16(const float2* __restrict__ s, __half2* __restrict__ hi, int n2) {
    int i = blockIdx.x * 256 + threadIdx.x;
    if (i >= n2) return;
    float2 v = s[i];
    hi[i] = __floats2half2_rn(v.x, v.y);
}
__global__ void convert_split_fp16(const float2* __restrict__ s,
                                   __half2* __restrict__ hi,
                                   __half2* __restrict__ lo, int n2) {
    int i = blockIdx.x * 256 + threadIdx.x;
    if (i >= n2) return;
    float2 v = s[i];
    __half h0 = __float2half_rn(v.x);
    __half h1 = __float2half_rn(v.y);
    hi[i] = __halves2half2(h0, h1);
    lo[i] = __floats2half2_rn(v.x - __half2float(h0), v.y - __half2float(h1));
}

// ---------------- RoPE + head split + fp16 + tiled V transpose -------------------
__global__ void __launch_bounds__(256)
rope_split2_kernel() {
    __shared__ __half vsm[128 * 40];
    int t0 = blockIdx.x * 32;
    int h = blockIdx.y;
    int b = blockIdx.z;
    int tid = threadIdx.x;
    int tt = tid >> 3;
    int pb = (tid & 7) * 8;
    int t = t0 + tt;
    int bh = b * NH + h;
    const float* base = g_qkv + (size_t)(b * TSEQ + t) * QKV_COLS;

    union U8 { __half h[8]; uint4 u[1]; };
    U8 qo1, qo2, kh1, kh2, kl1, kl2;
#pragma unroll
    for (int j = 0; j < 8; j++) {
        int d = pb + j;
        float c = g_cos[t * 64 + d];
        float s = g_sin[t * 64 + d];
        float q1 = base[h * HD + d];
        float q2 = base[h * HD + d + 64];
        float k1 = base[DM + h * HD + d];
        float k2 = base[DM + h * HD + d + 64];
        float qa = (q1 * c - q2 * s) * 0.08838834764831845f;
        float qb = (q1 * s + q2 * c) * 0.08838834764831845f;
        float ka = k1 * c - k2 * s;
        float kb = k1 * s + k2 * c;
        qo1.h[j] = __float2half_rn(qa);
        qo2.h[j] = __float2half_rn(qb);
        kh1.h[j] = __float2half_rn(ka);
        kl1.h[j] = __float2half_rn(ka - __half2float(kh1.h[j]));
        kh2.h[j] = __float2half_rn(kb);
        kl2.h[j] = __float2half_rn(kb - __half2float(kh2.h[j]));
        float v1 = base[2 * DM + h * HD + d];
        float v2 = base[2 * DM + h * HD + d + 64];
        vsm[d * 40 + tt] = __float2half_rn(v1);
        vsm[(d + 64) * 40 + tt] = __float2half_rn(v2);
    }
    size_t o = ((size_t)bh * TSEQ + t) * HD + pb;
    *(uint4*)(g_qh + o)      = qo1.u[0];
    *(uint4*)(g_qh + o + 64) = qo2.u[0];
    *(uint4*)(g_kh + o)      = kh1.u[0];
    *(uint4*)(g_kh + o + 64) = kh2.u[0];
    *(uint4*)(g_kl + o)      = kl1.u[0];
    *(uint4*)(g_kl + o + 64) = kl2.u[0];
    __syncthreads();

    int d = tid >> 1, th = (tid & 1) * 16;
    uint4 a = *(uint4*)(vsm + d * 40 + th);
    uint4 b2 = *(uint4*)(vsm + d * 40 + th + 8);
    __half* dst = g_vth + ((size_t)bh * HD + d) * TSEQ + t0 + th;
    *(uint4*)(dst) = a;
    *(uint4*)(dst + 8) = b2;
}

// ---------------- HMMA fp16 2-term GEMM, K64 2-stage, 64x32 warp tiles -----------
// C = Ah @ (Bh + Bl)^T + bias. 128x128x64 CTA tile, 8 warps (2m x 4n),
// warp tile 64x32, mma.sync.m16n8k16.
#define GROW 72                           // padded smem row (fp16 elems)
#define GTILE_B (128 * GROW * 2)          // 18432 bytes
#define GSTAGE_B (3 * GTILE_B)            // 55296 bytes (Ah, Bh, Bl)
#define G_SMEM_TOTAL (2 * GSTAGE_B)       // 110592 bytes, 2 stages

// load one 128x64 fp16 tile (128B/row) into padded smem rows
__device__ __forceinline__ void ld_tile64(uint32_t dst, const __half* g, int ldK) {
#pragma unroll
    for (int r = 0; r < 4; r++) {
        int idx = threadIdx.x + r * 256;
        int row = idx >> 3, c = idx & 7;
        cpa16(dst + (row * GROW + c * 8) * 2, g + (size_t)row * ldK + c * 8);
    }
}

__global__ void __launch_bounds__(256, 2)
gemm_fp16_2t(const __half* __restrict__ Ah,
             const __half* __restrict__ Bhi, const __half* __restrict__ Blo,
             const float* __restrict__ bias, float* __restrict__ C,
             int M, int N, int K) {
    extern __shared__ __align__(128) char sm[];
    uint32_t sb = smem_u32(sm);
    int tid = threadIdx.x, wid = tid >> 5, lane = tid & 31;
    int wm = wid & 1, wn = wid >> 1;            // warp tile origin (wm*64, wn*32)
    int bm = blockIdx.y * 128, bn = blockIdx.x * 128;

    const __half* Ap = Ah  + (size_t)bm * K;
    const __half* Bh = Bhi + (size_t)bn * K;
    const __half* Bl = Blo + (size_t)bn * K;

    float acc[4][4][4];                         // [mi][ni(n8)][frag]
#pragma unroll
    for (int i = 0; i < 4; i++)
#pragma unroll
        for (int j = 0; j < 4; j++)
#pragma unroll
            for (int k = 0; k < 4; k++) acc[i][j][k] = 0.f;

    int nc = K / 64;
#pragma unroll
    for (int s = 0; s < 2; s++) {
        uint32_t st = sb + s * GSTAGE_B;
        ld_tile64(st + 0 * GTILE_B, Ap + s * 64, K);
        ld_tile64(st + 1 * GTILE_B, Bh + s * 64, K);
        ld_tile64(st + 2 * GTILE_B, Bl + s * 64, K);
        asm volatile("cp.async.commit_group;" ::: "memory");
    }

    int lrow = lane & 15;
    int lcol8 = (lane >> 4) * 8;

    for (int i = 0; i < nc; i++) {
        if (i == nc - 1) asm volatile("cp.async.wait_group 0;" ::: "memory");
        else             asm volatile("cp.async.wait_group 1;" ::: "memory");
        __syncthreads();

        uint32_t st = sb + (uint32_t)(i & 1) * GSTAGE_B;
        uint32_t sA = st, sBh = st + GTILE_B, sBl = st + 2 * GTILE_B;

#pragma unroll
        for (int ks = 0; ks < 4; ks++) {
            int kc = ks * 16 + lcol8;
            uint32_t a[4][4], bh[2][4], bl[2][4];
#pragma unroll
            for (int mi = 0; mi < 4; mi++) {
                int r = wm * 64 + mi * 16 + lrow;
                ldm_x4(a[mi], sA + (r * GROW + kc) * 2);
            }
#pragma unroll
            for (int nb = 0; nb < 2; nb++) {
                int r = wn * 32 + nb * 16 + lrow;
                ldm_x4(bh[nb], sBh + (r * GROW + kc) * 2);
                ldm_x4(bl[nb], sBl + (r * GROW + kc) * 2);
            }
#pragma unroll
            for (int mi = 0; mi < 4; mi++)
#pragma unroll
                for (int nb = 0; nb < 2; nb++) {
                    mma16816h(acc[mi][2 * nb + 0], a[mi], bh[nb][0], bh[nb][2]);
                    mma16816h(acc[mi][2 * nb + 1], a[mi], bh[nb][1], bh[nb][3]);
                    mma16816h(acc[mi][2 * nb + 0], a[mi], bl[nb][0], bl[nb][2]);
                    mma16816h(acc[mi][2 * nb + 1], a[mi], bl[nb][1], bl[nb][3]);
                }
        }
        __syncthreads();
        if (i + 2 < nc) {
            int k0 = (i + 2) * 64;
            ld_tile64(st + 0 * GTILE_B, Ap + k0, K);
            ld_tile64(st + 1 * GTILE_B, Bh + k0, K);
            ld_tile64(st + 2 * GTILE_B, Bl + k0, K);
            asm volatile("cp.async.commit_group;" ::: "memory");
        }
    }

    int qrow = lane >> 2, qcol = (lane & 3) * 2;
#pragma unroll
    for (int mi = 0; mi < 4; mi++) {
#pragma unroll
        for (int ni = 0; ni < 4; ni++) {
            int c = bn + wn * 32 + ni * 8 + qcol;
            float b0 = bias[c], b1 = bias[c + 1];
            int r0 = bm + wm * 64 + mi * 16 + qrow;
            float2 v0 = make_float2(acc[mi][ni][0] + b0, acc[mi][ni][1] + b1);
            float2 v1 = make_float2(acc[mi][ni][2] + b0, acc[mi][ni][3] + b1);
            *(float2*)(C + (size_t)r0 * N + c) = v0;
            *(float2*)(C + (size_t)(r0 + 8) * N + c) = v1;
        }
    }
}

// ---------------- HMMA flash attention (causal), fp16 2-term ---------------------
#define ABM 128
#define ABN 64
#define QSTR 136
#define KSTR 136
#define VSTR 72
#define SM_Q  0
#define SM_KH (SM_Q + ABM * QSTR * 2)           // 34816
#define SM_KL (SM_KH + ABN * KSTR * 2)          // 52224
#define SM_V  (SM_KL + ABN * KSTR * 2)          // 69632
#define ATT_SMEM (SM_V + HD * VSTR * 2)         // 88064

__global__ void __launch_bounds__(256, 2)
attn_mma_kernel() {
    extern __shared__ __align__(128) char smA[];
    uint32_t sb = smem_u32(smA);
    int tid = threadIdx.x, wid = tid >> 5, lane = tid & 31;
    int qb = blockIdx.x;
    int bh = blockIdx.y;
    int lrow = lane & 15;
    int lcol8 = (lane >> 4) * 8;
    int qrow = lane >> 2, qcol = (lane & 3) * 2;

    {
        const __half* Q = g_qh + ((size_t)bh * TSEQ + qb * ABM) * HD;
#pragma unroll
        for (int i = 0; i < 8; i++) {
            int idx = tid + i * 256;
            int row = idx >> 4, c = idx & 15;
            cpa16(sb + SM_Q + (row * QSTR + c * 8) * 2, Q + (size_t)row * HD + c * 8);
        }
        asm volatile("cp.async.commit_group;" ::: "memory");
        asm volatile("cp.async.wait_group 0;" ::: "memory");
        __syncthreads();
    }

    float o[16][4];
#pragma unroll
    for (int i = 0; i < 16; i++)
#pragma unroll
        for (int j = 0; j < 4; j++) o[i][j] = 0.f;
    float m0 = -1e30f, m1 = -1e30f, l0 = 0.f, l1 = 0.f;

    int nkb = 2 * qb + 2;
    for (int kb = 0; kb < nkb; kb++) {
        {
            const __half* Kh = g_kh + ((size_t)bh * TSEQ + kb * ABN) * HD;
            const __half* Kl = g_kl + ((size_t)bh * TSEQ + kb * ABN) * HD;
#pragma unroll
            for (int i = 0; i < 4; i++) {
                int idx = tid + i * 256;
                int row = idx >> 4, c = idx & 15;
                cpa16(sb + SM_KH + (row * KSTR + c * 8) * 2, Kh + (size_t)row * HD + c * 8);
                cpa16(sb + SM_KL + (row * KSTR + c * 8) * 2, Kl + (size_t)row * HD + c * 8);
            }
            const __half* V = g_vth + (size_t)bh * HD * TSEQ + kb * ABN;
#pragma unroll
            for (int i = 0; i < 4; i++) {
                int idx = tid + i * 256;
                int row = idx >> 3, c = idx & 7;
                cpa16(sb + SM_V + (row * VSTR + c * 8) * 2, V + (size_t)row * TSEQ + c * 8);
            }
            asm volatile("cp.async.commit_group;" ::: "memory");
            asm volatile("cp.async.wait_group 0;" ::: "memory");
            __syncthreads();
        }

        float s[8][4];
#pragma unroll
        for (int i = 0; i < 8; i++)
#pragma unroll
            for (int j = 0; j < 4; j++) s[i][j] = 0.f;
#pragma unroll
        for (int kc = 0; kc < 8; kc++) {
            uint32_t a[4];
            ldm_x4(a, sb + SM_Q + ((wid * 16 + lrow) * QSTR + kc * 16 + lcol8) * 2);
#pragma unroll
            for (int nb = 0; nb < 4; nb++) {
                uint32_t bhh[4], bll[4];
                ldm_x4(bhh, sb + SM_KH + ((nb * 16 + lrow) * KSTR + kc * 16 + lcol8) * 2);
                ldm_x4(bll, sb + SM_KL + ((nb * 16 + lrow) * KSTR + kc * 16 + lcol8) * 2);
                mma16816h(s[2 * nb + 0], a, bhh[0], bhh[2]);
                mma16816h(s[2 * nb + 1], a, bhh[1], bhh[3]);
                mma16816h(s[2 * nb + 0], a, bll[0], bll[2]);
                mma16816h(s[2 * nb + 1], a, bll[1], bll[3]);
            }
        }

        if (kb >= 2 * qb) {
            int rg = qb * ABM + wid * 16 + qrow;
#pragma unroll
            for (int nb = 0; nb < 8; nb++) {
#pragma unroll
                for (int e = 0; e < 2; e++) {
                    int col = kb * ABN + nb * 8 + qcol + e;
                    if (col > rg)     s[nb][e]     = -1e30f;
                    if (col > rg + 8) s[nb][2 + e] = -1e30f;
                }
            }
        }

        float mx0 = -1e30f, mx1 = -1e30f;
#pragma unroll
        for (int nb = 0; nb < 8; nb++) {
            mx0 = fmaxf(mx0, fmaxf(s[nb][0], s[nb][1]));
            mx1 = fmaxf(mx1, fmaxf(s[nb][2], s[nb][3]));
        }
        mx0 = fmaxf(mx0, __shfl_xor_sync(0xffffffffu, mx0, 1));
        mx0 = fmaxf(mx0, __shfl_xor_sync(0xffffffffu, mx0, 2));
        mx1 = fmaxf(mx1, __shfl_xor_sync(0xffffffffu, mx1, 1));
        mx1 = fmaxf(mx1, __shfl_xor_sync(0xffffffffu, mx1, 2));
        float mn0 = fmaxf(m0, mx0), mn1 = fmaxf(m1, mx1);
        float a0 = __expf(m0 - mn0), a1 = __expf(m1 - mn1);
        float sum0 = 0.f, sum1 = 0.f;
#pragma unroll
        for (int nb = 0; nb < 8; nb++) {
            s[nb][0] = __expf(s[nb][0] - mn0); sum0 += s[nb][0];
            s[nb][1] = __expf(s[nb][1] - mn0); sum0 += s[nb][1];
            s[nb][2] = __expf(s[nb][2] - mn1); sum1 += s[nb][2];
            s[nb][3] = __expf(s[nb][3] - mn1); sum1 += s[nb][3];
        }
        sum0 += __shfl_xor_sync(0xffffffffu, sum0, 1);
        sum0 += __shfl_xor_sync(0xffffffffu, sum0, 2);
        sum1 += __shfl_xor_sync(0xffffffffu, sum1, 1);
        sum1 += __shfl_xor_sync(0xffffffffu, sum1, 2);
        l0 = l0 * a0 + sum0; l1 = l1 * a1 + sum1;
        m0 = mn0; m1 = mn1;
#pragma unroll
        for (int nb = 0; nb < 16; nb++) {
            o[nb][0] *= a0; o[nb][1] *= a0;
            o[nb][2] *= a1; o[nb][3] *= a1;
        }

#pragma unroll
        for (int kk = 0; kk < 4; kk++) {
            uint32_t pah[4], pal[4];
            split2h(s[2 * kk][0],     s[2 * kk][1],     pah[0], pal[0]);
            split2h(s[2 * kk][2],     s[2 * kk][3],     pah[1], pal[1]);
            split2h(s[2 * kk + 1][0], s[2 * kk + 1][1], pah[2], pal[2]);
            split2h(s[2 * kk + 1][2], s[2 * kk + 1][3], pah[3], pal[3]);
#pragma unroll
            for (int blk = 0; blk < 8; blk++) {
                uint32_t vb[4];
                ldm_x4(vb, sb + SM_V + ((blk * 16 + lrow) * VSTR + kk * 16 + lcol8) * 2);
                mma16816h(o[2 * blk + 0], pah, vb[0], vb[2]);
                mma16816h(o[2 * blk + 1], pah, vb[1], vb[3]);
                mma16816h(o[2 * blk + 0], pal, vb[0], vb[2]);
                mma16816h(o[2 * blk + 1], pal, vb[1], vb[3]);
            }
        }
        __syncthreads();
    }

    float inv0 = 1.0f / l0, inv1 = 1.0f / l1;
    int b = bh >> 4, h = bh & 15;
    int r0 = qb * ABM + wid * 16 + qrow;
    float* base0 = g_ctx + ((size_t)(b * TSEQ + r0)) * DM + h * HD + qcol;
    float* base1 = g_ctx + ((size_t)(b * TSEQ + r0 + 8)) * DM + h * HD + qcol;
#pragma unroll
    for (int nb = 0; nb < 16; nb++) {
        *(float2*)(base0 + nb * 8) = make_float2(o[nb][0] * inv0, o[nb][1] * inv0);
        *(float2*)(base1 + nb * 8) = make_float2(o[nb][2] * inv1, o[nb][3] * inv1);
    }
}

// ---------------- launcher --------------------------------------------------------
extern "C" void kernel_launch(void* const* d_in, const int* in_sizes, int n_in,
                              void* d_out, int out_size) {
    const float* x    = (const float*)d_in[0];
    const float* Wqkv = (const float*)d_in[1];
    const float* bqkv = (const float*)d_in[2];
    const float* Wo   = (const float*)d_in[3];
    const float* bo   = (const float*)d_in[4];
    float* out = (float*)d_out;

    float *qkv_p, *ctx_p;
    cudaGetSymbolAddress((void**)&qkv_p, g_qkv);
    cudaGetSymbolAddress((void**)&ctx_p, g_ctx);
    __half *xh, *wqh, *wql, *woh, *wol, *ch;
    cudaGetSymbolAddress((void**)&xh, g_xh);
    cudaGetSymbolAddress((void**)&wqh, g_wqkvh);
    cudaGetSymbolAddress((void**)&wql, g_wqkvl);
    cudaGetSymbolAddress((void**)&woh, g_woh);
    cudaGetSymbolAddress((void**)&wol, g_wol);
    cudaGetSymbolAddress((void**)&ch, g_ch);

    cudaFuncSetAttribute(gemm_fp16_2t,
                         cudaFuncAttributeMaxDynamicSharedMemorySize, G_SMEM_TOTAL);
    cudaFuncSetAttribute(attn_mma_kernel,
                         cudaFuncAttributeMaxDynamicSharedMemorySize, ATT_SMEM);

    // 1) RoPE table
    rope_table_kernel<<<(TSEQ * (HD / 2) + 255) / 256, 256>>>();

    // 2) converts: x -> fp16 hi; Wqkv -> fp16 hi/lo
    {
        int n2 = (NTOK * DM) / 2;
        convert_hi_fp16<<<(n2 + 255) / 256, 256>>>((const float2*)x, (__half2*)xh, n2);
        n2 = (QKV_COLS * DM) / 2;
        convert_split_fp16<<<(n2 + 255) / 256, 256>>>((const float2*)Wqkv,
            (__half2*)wqh, (__half2*)wql, n2);
    }

    // 3) QKV projection (fp16 2-term HMMA, K64 2-stage, 64x32 warp tiles)
    {
        dim3 grid(QKV_COLS / 128, NTOK / 128);
        gemm_fp16_2t<<<grid, 256, G_SMEM_TOTAL>>>(xh, wqh, wql, bqkv, qkv_p,
                                                  NTOK, QKV_COLS, DM);
    }

    // 4) RoPE + head split + fp16 + tiled V transpose
    {
        dim3 grid(TSEQ / 32, NH, BB);
        rope_split2_kernel<<<grid, 256>>>();
    }

    // 5) causal flash attention (fp16 2-term HMMA)
    {
        dim3 grid(TSEQ / ABM, BB * NH);
        attn_mma_kernel<<<grid, 256, ATT_SMEM>>>();
    }

    // 6) converts: ctx -> fp16 hi; Wo -> fp16 hi/lo
    {
        int n2 = (NTOK * DM) / 2;
        convert_hi_fp16<<<(n2 + 255) / 256, 256>>>((const float2*)ctx_p, (__half2*)ch, n2);
        n2 = (DM * DM) / 2;
        convert_split_fp16<<<(n2 + 255) / 256, 256>>>((const float2*)Wo,
            (__half2*)woh, (__half2*)wol, n2);
    }

    // 7) output projection (fp16 2-term HMMA)
    {
        dim3 grid(DM / 128, NTOK / 128);
        gemm_fp16_2t<<<grid, 256, G_SMEM_TOTAL>>>(ch, woh, wol, bo, out,
                                                  NTOK, DM, DM);
    }
}